// round 13
// baseline (speedup 1.0000x reference)
#include <cuda_runtime.h>
#include <cuda_bf16.h>

// ---------------------------------------------------------------------------
// ASLRNN3 sm_100a.
//  * only last frame feeds outs[-1]
//  * hidden recurrence: affine, i2h-independent -> homogeneous 501x501 power
//    (512-pad). ENTIRE chain (pad + 5 squarings + reduces + hidden GEMM) in
//    ONE persistent kernel: 256 blocks = split-K 4 INSIDE the kernel, grid
//    barriers between phases. Run strictly SEQUENTIALLY so barriers never
//    straggle. R12 bugs fixed: pad loop now grid-stride (covers all 512^2),
//    cross-block re-read data uses .cg (L2 coherence point; L1 is stale
//    inside a single kernel).
//  * all GEMMs: bf16 hi/lo split 3-MMA, fp32 accum, cp.async.cg, ldmatrix.
// ---------------------------------------------------------------------------

#define NB 512
#define FEAT 304
#define HF 300
#define YK 9504
#define HID 500
#define HIDP 512
#define OUT 10
#define L2S 11         // l2 split-K  (9504 = 11*864, 864 = 27*32)
#define L2LEN 864
#define CHB 256        // chain grid: 64 tiles x 4 split-K
#define CHS 4
#define CHLEN 128      // 4 k-iters of 32

typedef __nv_bfloat16 bf;

// ---- scratch ----
__device__ bf g_feath[1024 * FEAT];
__device__ bf g_featl[1024 * FEAT];
__device__ float g_both[1024 * HF];
__device__ bf g_yh[NB * YK];
__device__ bf g_yl[NB * YK];
__device__ float g_part[L2S * NB * HID];
__device__ float g_cpart[CHS * HIDP * HIDP];
__device__ float g_hpart[CHS * NB * HID];
__device__ bf g_Wh [HIDP * HIDP];
__device__ bf g_Wl [HIDP * HIDP];
__device__ bf g_WTh[HIDP * HIDP];
__device__ bf g_WTl[HIDP * HIDP];
__device__ bf g_M0h[HIDP * HIDP];
__device__ bf g_M0l[HIDP * HIDP];
__device__ bf g_M0Th[HIDP * HIDP];
__device__ bf g_M0Tl[HIDP * HIDP];
__device__ bf g_M1h[HIDP * HIDP];
__device__ bf g_M1l[HIDP * HIDP];
__device__ bf g_M1Th[HIDP * HIDP];
__device__ bf g_M1Tl[HIDP * HIDP];
__device__ bf g_h0h[NB * HIDP];
__device__ bf g_h0l[NB * HIDP];
__device__ float g_hid[NB * HID];

// software grid barrier state (generation-based; graph-replay safe)
__device__ unsigned g_cnt = 0;
__device__ volatile unsigned g_gen = 0;

#define MMA16816(c, a, b) asm volatile( \
    "mma.sync.aligned.m16n8k16.row.col.f32.bf16.bf16.f32 " \
    "{%0,%1,%2,%3},{%4,%5,%6,%7},{%8,%9},{%0,%1,%2,%3};\n" \
    : "+f"((c)[0]), "+f"((c)[1]), "+f"((c)[2]), "+f"((c)[3]) \
    : "r"((a)[0]), "r"((a)[1]), "r"((a)[2]), "r"((a)[3]), \
      "r"((b)[0]), "r"((b)[1]))

__device__ __forceinline__ void split_pair(float x, bf& h, bf& l) {
    h = __float2bfloat16(x);
    l = __float2bfloat16(x - __bfloat162float(h));
}
// L2-only async copy (16B): coherent with other blocks' stores in-kernel.
__device__ __forceinline__ void cp16(unsigned dst, const void* src) {
    asm volatile("cp.async.cg.shared.global [%0], [%1], 16;\n" :: "r"(dst), "l"(src));
}
#define CP_COMMIT asm volatile("cp.async.commit_group;\n")

#define SA 40
#define ARRE (64 * SA)

__device__ __forceinline__ void ldsm4(unsigned addr, unsigned* r) {
    asm volatile("ldmatrix.sync.aligned.m8n8.x4.shared.b16 {%0,%1,%2,%3}, [%4];"
        : "=r"(r[0]), "=r"(r[1]), "=r"(r[2]), "=r"(r[3]) : "r"(addr));
}

__device__ __forceinline__ void grid_bar() {
    __syncthreads();
    if (threadIdx.x == 0) {
        __threadfence();
        const unsigned gen = g_gen;
        if (atomicAdd(&g_cnt, 1u) == CHB - 1) {
            g_cnt = 0;
            __threadfence();
            g_gen = gen + 1;
        } else {
            while (g_gen == gen) { __nanosleep(32); }
        }
        __threadfence();
    }
    __syncthreads();
}

// hi/lo 3-MMA over NS 16-k-steps using ldmatrix fragment loads.
template<int ST, int ARR, int NS>
__device__ __forceinline__ void stage_mma_u(unsigned base, int wm, int wn,
                                            int lane, float acc[2][2][4])
{
    constexpr unsigned AB = ARR * 2;
    const int arow = lane & 15;
    const int acol = (lane >> 4) * 8;
    const int bg   = lane >> 3;
    const int brow = (bg >> 1) * 8 + (lane & 7);
    const int bcol = (bg & 1) * 8;
    #pragma unroll
    for (int s = 0; s < NS; ++s) {
        const int kb = s * 16;
        unsigned a_h[2][4], a_l[2][4], b_h[4], b_l[4];
        #pragma unroll
        for (int mt = 0; mt < 2; ++mt) {
            const unsigned ao = (unsigned)(((wm + mt * 16 + arow) * ST + kb + acol) * 2);
            ldsm4(base + ao,      a_h[mt]);
            ldsm4(base + AB + ao, a_l[mt]);
        }
        const unsigned bo = (unsigned)(((wn + brow) * ST + kb + bcol) * 2);
        ldsm4(base + 2 * AB + bo, b_h);
        ldsm4(base + 3 * AB + bo, b_l);
        #pragma unroll
        for (int mt = 0; mt < 2; ++mt)
            #pragma unroll
            for (int nt = 0; nt < 2; ++nt) {
                MMA16816(acc[mt][nt], a_h[mt], b_h + nt * 2);
                MMA16816(acc[mt][nt], a_h[mt], b_l + nt * 2);
                MMA16816(acc[mt][nt], a_l[mt], b_h + nt * 2);
            }
    }
}

// ---------------------------------------------------------------------------
// Persistent chain kernel: pad/split -> 5x (split-K=4 squaring + in-kernel
// reduce) -> hidden partials. ONE launch, 256 blocks, run alone.
// ---------------------------------------------------------------------------
__global__ __launch_bounds__(256, 2)
void chain_kernel(const float* __restrict__ W, const float* __restrict__ b,
                  const float* __restrict__ h0)
{
    __shared__ __align__(16) bf sm[2 * 4 * ARRE];   // 40 KB
    const unsigned smb = (unsigned)__cvta_generic_to_shared(sm);
    constexpr unsigned ARRB = ARRE * 2;
    constexpr unsigned STAGEB = 4 * ARRB;

    const int tid  = threadIdx.x;
    const int wid  = tid >> 5;
    const int lane = tid & 31;
    const int wm   = (wid >> 2) * 32;
    const int wn   = (wid & 3) * 16;
    const int lr   = lane >> 2;
    const int lc   = lane & 3;
    const int bid  = blockIdx.x;
    const int bz   = bid >> 6;            // split-K slice 0..3
    const int tile = bid & 63;
    const int m0   = (tile >> 3) * 64;
    const int n0   = (tile & 7) * 64;
    const int kbeg = bz * CHLEN;

    // ---- phase 0: pad + split W (and W^T) and h0aug (grid-stride: 4/thread)
    for (int idx = bid * 256 + tid; idx < HIDP * HIDP; idx += CHB * 256) {
        const int r = idx >> 9, c = idx & (HIDP - 1);
        float wv = 0.f;
        if (r < HID) {
            if (c < HID) wv = W[r * HID + c];
            else if (c == HID) wv = b[r];
        } else if (r == HID && c == HID) wv = 1.f;
        bf h, l;
        split_pair(wv, h, l);
        g_Wh[idx] = h;  g_Wl[idx] = l;
        g_WTh[c * HIDP + r] = h;  g_WTl[c * HIDP + r] = l;
        float hv = (c < HID) ? h0[r * HID + c] : (c == HID ? 1.f : 0.f);
        split_pair(hv, g_h0h[idx], g_h0l[idx]);
    }
    grid_bar();

    const int ar = tid >> 2;
    const int ac = (tid & 3) * 8;

    auto do_gemm = [&](const bf* Agh, const bf* Agl,
                       const bf* Bgh, const bf* Bgl, float acc[2][2][4]) {
        auto issue = [&](int k0, int st) {
            const size_t ao = (size_t)(m0 + ar) * HIDP + k0 + ac;
            const size_t bo = (size_t)(n0 + ar) * HIDP + k0 + ac;
            const unsigned d = smb + st * STAGEB + (unsigned)(ar * SA + ac) * 2;
            cp16(d,            Agh + ao);
            cp16(d + ARRB,     Agl + ao);
            cp16(d + 2 * ARRB, Bgh + bo);
            cp16(d + 3 * ARRB, Bgl + bo);
            CP_COMMIT;
        };
        constexpr int nit = CHLEN / 32;
        issue(kbeg, 0);
        #pragma unroll
        for (int i = 0; i < nit; ++i) {
            if (i + 1 < nit) {
                issue(kbeg + (i + 1) * 32, (i + 1) & 1);
                asm volatile("cp.async.wait_group 1;\n");
            } else {
                asm volatile("cp.async.wait_group 0;\n");
            }
            __syncthreads();
            stage_mma_u<SA, ARRE, 2>(smb + (i & 1) * STAGEB, wm, wn, lane, acc);
            __syncthreads();
        }
    };

    // ---- phases 1..5: squarings with in-kernel split-K reduce
    const bf *sh = g_Wh, *sl = g_Wl, *sth = g_WTh, *stl = g_WTl;
    bf* dh [5] = { g_M0h,  g_M1h,  g_M0h,  g_M1h,  g_M0h  };
    bf* dl [5] = { g_M0l,  g_M1l,  g_M0l,  g_M1l,  g_M0l  };
    bf* dth[5] = { g_M0Th, g_M1Th, g_M0Th, g_M1Th, g_M0Th };
    bf* dtl[5] = { g_M0Tl, g_M1Tl, g_M0Tl, g_M1Tl, g_M0Tl };

    for (int it = 0; it < 5; ++it) {
        float acc[2][2][4] = {};
        do_gemm(sh, sl, sth, stl, acc);

        // write fp32 partial for this split slice
        float* P = g_cpart + (size_t)bz * HIDP * HIDP;
        #pragma unroll
        for (int mt = 0; mt < 2; ++mt)
            #pragma unroll
            for (int nt = 0; nt < 2; ++nt)
                #pragma unroll
                for (int rr = 0; rr < 2; ++rr) {
                    const int r = m0 + wm + mt * 16 + lr + rr * 8;
                    #pragma unroll
                    for (int j = 0; j < 2; ++j) {
                        const int c = n0 + wn + nt * 8 + lc * 2 + j;
                        P[(size_t)r * HIDP + c] = acc[mt][nt][rr * 2 + j];
                    }
                }
        grid_bar();

        // distributed reduce: block bid owns 32x32 tile (bid>>4, bid&15).
        // .cg loads — L1 holds stale lines from previous iterations.
        {
            bf* th = sm;                     // [32][33]
            bf* tl = sm + 32 * 33;
            const int by2 = (bid >> 4) * 32;
            const int bx2 = (bid & 15) * 32;
            const int x  = tid & 31;
            const int y0 = tid >> 5;
            #pragma unroll
            for (int dy = 0; dy < 32; dy += 8) {
                const int r = by2 + y0 + dy, c = bx2 + x;
                const size_t idx = (size_t)r * HIDP + c;
                float v = __ldcg(&g_cpart[idx]);
                #pragma unroll
                for (int s = 1; s < CHS; ++s)
                    v += __ldcg(&g_cpart[(size_t)s * HIDP * HIDP + idx]);
                bf h, l;
                split_pair(v, h, l);
                dh[it][idx] = h; dl[it][idx] = l;
                th[(y0 + dy) * 33 + x] = h;
                tl[(y0 + dy) * 33 + x] = l;
            }
            if (it < 4) {
                __syncthreads();
                #pragma unroll
                for (int dy = 0; dy < 32; dy += 8) {
                    const int r = bx2 + y0 + dy, c = by2 + x;
                    const size_t idx = (size_t)r * HIDP + c;
                    dth[it][idx] = th[x * 33 + y0 + dy];
                    dtl[it][idx] = tl[x * 33 + y0 + dy];
                }
            }
        }
        grid_bar();
        sh = dh[it]; sl = dl[it]; sth = dth[it]; stl = dtl[it];
    }

    // ---- phase 6: hidden partials = h0aug @ (W^32)^T  (B = M32 pair)
    {
        float acc[2][2][4] = {};
        do_gemm(g_h0h, g_h0l, sh, sl, acc);
        float* P = g_hpart + (size_t)bz * NB * HID;
        #pragma unroll
        for (int mt = 0; mt < 2; ++mt)
            #pragma unroll
            for (int nt = 0; nt < 2; ++nt)
                #pragma unroll
                for (int rr = 0; rr < 2; ++rr) {
                    const int r = m0 + wm + mt * 16 + lr + rr * 8;
                    #pragma unroll
                    for (int j = 0; j < 2; ++j) {
                        const int c = n0 + wn + nt * 8 + lc * 2 + j;
                        if (c < HID) P[(size_t)r * HID + c] = acc[mt][nt][rr * 2 + j];
                    }
                }
    }
}

// ---------------------------------------------------------------------------
// l2_gemm: pair A (cp.async), fp32 B (register-prefetch + split in staging),
// split-K -> fp32 partials. B is (N,K)=(500,9504) row-major fp32.
// ---------------------------------------------------------------------------
__global__ __launch_bounds__(256)
void l2_gemm(const bf* __restrict__ Agh, const bf* __restrict__ Agl,
             const float* __restrict__ Bf,
             float* __restrict__ C)
{
    __shared__ __align__(16) bf sm[2 * 4 * ARRE];
    const unsigned smb = (unsigned)__cvta_generic_to_shared(sm);
    constexpr unsigned ARRB = ARRE * 2;
    constexpr unsigned STAGEB = 4 * ARRB;

    const int tid  = threadIdx.x;
    const int wid  = tid >> 5;
    const int lane = tid & 31;
    const int wm   = (wid >> 2) * 32;
    const int wn   = (wid & 3) * 16;
    const int lr   = lane >> 2;
    const int lc   = lane & 3;
    const int m0   = blockIdx.y * 64;
    const int n0   = blockIdx.x * 64;
    const int kbeg = blockIdx.z * L2LEN;
    C += (size_t)blockIdx.z * (size_t)NB * (size_t)HID;

    float acc[2][2][4] = {};
    const int ar = tid >> 2;
    const int ac = (tid & 3) * 8;
    const bool bvalid = (n0 + ar) < HID;
    const float* brow = Bf + (size_t)(n0 + ar) * YK;

    float4 rB0, rB1;

    auto issueA = [&](int k0, int st) {
        const size_t ao = (size_t)(m0 + ar) * YK + k0 + ac;
        const unsigned d = smb + st * STAGEB + (unsigned)(ar * SA + ac) * 2;
        cp16(d,        Agh + ao);
        cp16(d + ARRB, Agl + ao);
        CP_COMMIT;
    };
    auto loadB = [&](int k0) {
        if (bvalid) {
            rB0 = *reinterpret_cast<const float4*>(brow + k0 + ac);
            rB1 = *reinterpret_cast<const float4*>(brow + k0 + ac + 4);
        } else {
            rB0 = make_float4(0.f, 0.f, 0.f, 0.f);
            rB1 = make_float4(0.f, 0.f, 0.f, 0.f);
        }
    };
    auto storeB = [&](int st) {
        bf* Bh = sm + st * 4 * ARRE + 2 * ARRE + ar * SA + ac;
        bf* Bl = Bh + ARRE;
        const float v[8] = { rB0.x, rB0.y, rB0.z, rB0.w, rB1.x, rB1.y, rB1.z, rB1.w };
        uint4 vh, vl;
        bf* hv = reinterpret_cast<bf*>(&vh);
        bf* lv = reinterpret_cast<bf*>(&vl);
        #pragma unroll
        for (int e = 0; e < 8; ++e) split_pair(v[e], hv[e], lv[e]);
        *reinterpret_cast<uint4*>(Bh) = vh;
        *reinterpret_cast<uint4*>(Bl) = vl;
    };

    constexpr int nit = L2LEN / 32;
    issueA(kbeg, 0);
    loadB(kbeg);
    for (int i = 0; i < nit; ++i) {
        if (i + 1 < nit) issueA(kbeg + (i + 1) * 32, (i + 1) & 1);
        storeB(i & 1);
        if (i + 1 < nit) asm volatile("cp.async.wait_group 1;\n");
        else             asm volatile("cp.async.wait_group 0;\n");
        __syncthreads();
        if (i + 1 < nit) loadB(kbeg + (i + 1) * 32);
        stage_mma_u<SA, ARRE, 2>(smb + (i & 1) * STAGEB, wm, wn, lane, acc);
        __syncthreads();
    }

    #pragma unroll
    for (int mt = 0; mt < 2; ++mt)
        #pragma unroll
        for (int nt = 0; nt < 2; ++nt)
            #pragma unroll
            for (int rr = 0; rr < 2; ++rr) {
                const int r = m0 + wm + mt * 16 + lr + rr * 8;
                #pragma unroll
                for (int j = 0; j < 2; ++j) {
                    const int c = n0 + wn + nt * 8 + lc * 2 + j;
                    if (c < HID) C[(size_t)r * HID + c] = acc[mt][nt][rr * 2 + j];
                }
            }
}

// ---------------------------------------------------------------------------
// fc GEMM with register-prefetch double buffering (fp32 dual weights).
#define FSA 24
#define FARRE (64 * FSA)
__global__ __launch_bounds__(256)
void fc_gemm(const bf* __restrict__ Agh, const bf* __restrict__ Agl,
             const float* __restrict__ Bf, const float* __restrict__ bias,
             const float* __restrict__ Bf2, const float* __restrict__ bias2,
             float* __restrict__ C)
{
    constexpr int BK = 16;
    __shared__ __align__(16) bf smf[4 * FARRE];
    const unsigned smbf = (unsigned)__cvta_generic_to_shared(smf);
    bf* Ah = smf;
    bf* Al = smf + FARRE;
    bf* Bh = smf + 2 * FARRE;
    bf* Bl = smf + 3 * FARRE;

    const int tid  = threadIdx.x;
    const int wid  = tid >> 5;
    const int lane = tid & 31;
    const int wm   = (wid >> 2) * 32;
    const int wn   = (wid & 3) * 16;
    const int lr   = lane >> 2;
    const int lc   = lane & 3;
    const int m0   = blockIdx.y * 64;
    const int n0   = blockIdx.x * 64;
    const int N = HF, K = FEAT;

    if (blockIdx.y >= (gridDim.y >> 1)) { Bf = Bf2; bias = bias2; }

    float acc[2][2][4] = {};
    const int ar = tid >> 2;
    const int ac = (tid & 3) * 4;

    uint2 rAh, rAl;
    float4 rB;

    auto loadT = [&](int k0) {
        const size_t aoff = (size_t)(m0 + ar) * K + k0 + ac;
        rAh = *reinterpret_cast<const uint2*>(Agh + aoff);
        rAl = *reinterpret_cast<const uint2*>(Agl + aoff);
        if (n0 + ar < N)
            rB = *reinterpret_cast<const float4*>(&Bf[(size_t)(n0 + ar) * K + k0 + ac]);
        else
            rB = make_float4(0.f, 0.f, 0.f, 0.f);
    };
    auto storeT = [&]() {
        *reinterpret_cast<uint2*>(Ah + ar * FSA + ac) = rAh;
        *reinterpret_cast<uint2*>(Al + ar * FSA + ac) = rAl;
        split_pair(rB.x, Bh[ar * FSA + ac + 0], Bl[ar * FSA + ac + 0]);
        split_pair(rB.y, Bh[ar * FSA + ac + 1], Bl[ar * FSA + ac + 1]);
        split_pair(rB.z, Bh[ar * FSA + ac + 2], Bl[ar * FSA + ac + 2]);
        split_pair(rB.w, Bh[ar * FSA + ac + 3], Bl[ar * FSA + ac + 3]);
    };

    loadT(0);
    for (int k0 = 0; k0 < K; k0 += BK) {
        storeT();
        __syncthreads();
        if (k0 + BK < K) loadT(k0 + BK);
        stage_mma_u<FSA, FARRE, 1>(smbf, wm, wn, lane, acc);
        __syncthreads();
    }

    #pragma unroll
    for (int mt = 0; mt < 2; ++mt)
        #pragma unroll
        for (int nt = 0; nt < 2; ++nt)
            #pragma unroll
            for (int rr = 0; rr < 2; ++rr) {
                const int r = m0 + wm + mt * 16 + lr + rr * 8;
                #pragma unroll
                for (int j = 0; j < 2; ++j) {
                    const int c = n0 + wn + nt * 8 + lc * 2 + j;
                    if (c < N)
                        C[(size_t)r * HF + c] = fmaxf(acc[mt][nt][rr * 2 + j] + bias[c], 0.f);
                }
            }
}

// ---------------------------------------------------------------------------
// hand branch: conv1d(k=2,2->16) + relu + pool2 -> feat pair
__global__ void hand_feat_kernel(const float* __restrict__ hd,
                                 const float* __restrict__ lcw, const float* __restrict__ lcb,
                                 const float* __restrict__ rcw, const float* __restrict__ rcb,
                                 int tOff)
{
    const int s    = blockIdx.x;
    const int n    = s & (NB - 1);
    const int hand = s >> 9;
    const float* x  = hd + tOff + n * 84 + hand * 42;
    const float* cw = hand ? rcw : lcw;
    const float* cb = hand ? rcb : lcb;

    __shared__ float xs[42];
    __shared__ float z[16 * 20];
    const int tid = threadIdx.x;
    if (tid < 42) xs[tid] = x[tid];
    __syncthreads();

    for (int idx = tid; idx < 320; idx += 128) {
        int o = idx / 20, j = idx % 20;
        float v = cb[o]
                + cw[o * 4 + 0] * xs[2 * j]
                + cw[o * 4 + 1] * xs[2 * j + 2]
                + cw[o * 4 + 2] * xs[2 * j + 1]
                + cw[o * 4 + 3] * xs[2 * j + 3];
        z[o * 20 + j] = fmaxf(v, 0.f);
    }
    __syncthreads();

    for (int idx = tid; idx < FEAT; idx += 128) {
        int o = idx / 19, j = idx % 19;
        float v = fmaxf(z[o * 20 + j], z[o * 20 + j + 1]);
        split_pair(v, g_feath[(size_t)s * FEAT + idx], g_featl[(size_t)s * FEAT + idx]);
    }
}

// conv2(k=2,2->32) + relu + pool3 -> y pair; 2 blocks per sample (16 ch each)
__global__ __launch_bounds__(256)
void conv2pool_kernel(const float* __restrict__ w2, const float* __restrict__ b2)
{
    __shared__ float slo[HF], sro[HF], sw[128], sb[32];
    const int n    = blockIdx.x;
    const int half = blockIdx.y;
    const int tid  = threadIdx.x;
    const int wid  = tid >> 5;
    const int lane = tid & 31;
    for (int i = tid; i < HF; i += 256) {
        slo[i] = g_both[(size_t)n * HF + i];
        sro[i] = g_both[(size_t)(NB + n) * HF + i];
    }
    if (tid < 128) sw[tid] = w2[tid];
    if (tid < 32)  sb[tid] = b2[tid];
    __syncthreads();

    #pragma unroll
    for (int oo = 0; oo < 2; ++oo) {
        const int o = half * 16 + oo * 8 + wid;
        const float w00 = sw[o * 4 + 0], w01 = sw[o * 4 + 1];
        const float w10 = sw[o * 4 + 2], w11 = sw[o * 4 + 3];
        const float bb = sb[o];
        const size_t obase = (size_t)n * YK + o * 297;
        for (int jj = lane; jj < 297; jj += 32) {
            float l0 = slo[jj], l1 = slo[jj + 1], l2v = slo[jj + 2], l3 = slo[jj + 3];
            float r0 = sro[jj], r1 = sro[jj + 1], r2v = sro[jj + 2], r3 = sro[jj + 3];
            float z0 = bb + w00 * l0  + w01 * l1  + w10 * r0  + w11 * r1;
            float z1 = bb + w00 * l1  + w01 * l2v + w10 * r1  + w11 * r2v;
            float z2 = bb + w00 * l2v + w01 * l3  + w10 * r2v + w11 * r3;
            float v = fmaxf(fmaxf(z0, z1), fmaxf(z2, 0.f));
            split_pair(v, g_yh[obase + jj], g_yl[obase + jj]);
        }
    }
}

// final: hidden = sum(hpart); i2h = sum(part)+l2b; out = relu((i2h+hidden)@ow^T+ob)
__global__ __launch_bounds__(512)
void out_kernel(const float* __restrict__ part,
                const float* __restrict__ hpart,
                const float* __restrict__ l2b,
                const float* __restrict__ ow,
                const float* __restrict__ ob,
                float* __restrict__ out,
                float* __restrict__ hidOut)
{
    __shared__ float val[HID];
    const int n   = blockIdx.x;
    const int tid = threadIdx.x;

    if (tid < HID) {
        const size_t o = (size_t)n * HID + tid;
        float hs = hpart[o];
        #pragma unroll
        for (int s = 1; s < CHS; ++s) hs += hpart[(size_t)s * NB * HID + o];
        float is = l2b[tid];
        #pragma unroll
        for (int s = 0; s < L2S; ++s) is += part[(size_t)s * NB * HID + o];
        hidOut[o] = hs;
        val[tid] = hs + is;
    }
    __syncthreads();

    if (tid < OUT * 32) {
        const int m    = tid >> 5;
        const int lane = tid & 31;
        const float* w = ow + (size_t)m * HID;
        float s = 0.f;
        for (int k = lane; k < HID; k += 32) s += val[k] * w[k];
        #pragma unroll
        for (int o = 16; o; o >>= 1) s += __shfl_down_sync(0xffffffffu, s, o);
        if (lane == 0) out[n * OUT + m] = fmaxf(s + ob[m], 0.f);
    }
}

// ---------------------------------------------------------------------------
extern "C" void kernel_launch(void* const* d_in, const int* in_sizes, int n_in,
                              void* d_out, int out_size)
{
    const float* hand_data = (const float*)d_in[0];
    const float* hidden    = (const float*)d_in[1];
    const float* l_conv_w  = (const float*)d_in[2];
    const float* l_conv_b  = (const float*)d_in[3];
    const float* l_fc_w    = (const float*)d_in[4];
    const float* l_fc_b    = (const float*)d_in[5];
    const float* r_conv_w  = (const float*)d_in[6];
    const float* r_conv_b  = (const float*)d_in[7];
    const float* r_fc_w    = (const float*)d_in[8];
    const float* r_fc_b    = (const float*)d_in[9];
    const float* conv2_w   = (const float*)d_in[10];
    const float* conv2_b   = (const float*)d_in[11];
    const float* l2_w      = (const float*)d_in[12];
    const float* l2_b      = (const float*)d_in[13];
    const float* h2h_w     = (const float*)d_in[14];
    const float* h2h_b     = (const float*)d_in[15];
    const float* out_w     = (const float*)d_in[16];
    const float* out_b     = (const float*)d_in[17];

    const int T    = in_sizes[0] / (NB * 84);
    const int tOff = (T - 1) * NB * 84;

    bf *feath, *featl, *yh, *yl;
    float *both, *part, *hpart, *hid;
    cudaGetSymbolAddress((void**)&feath, g_feath);
    cudaGetSymbolAddress((void**)&featl, g_featl);
    cudaGetSymbolAddress((void**)&both,  g_both);
    cudaGetSymbolAddress((void**)&yh,    g_yh);
    cudaGetSymbolAddress((void**)&yl,    g_yl);
    cudaGetSymbolAddress((void**)&part,  g_part);
    cudaGetSymbolAddress((void**)&hpart, g_hpart);
    cudaGetSymbolAddress((void**)&hid,   g_hid);

    float* hidOut = (out_size >= NB * OUT + NB * HID) ? ((float*)d_out) + NB * OUT : hid;

    // Strictly sequential on the default stream. The persistent chain kernel
    // must run ALONE so its grid barrier never waits on SM contention.
    chain_kernel<<<CHB, 256>>>(h2h_w, h2h_b, hidden);
    hand_feat_kernel<<<1024, 128>>>(hand_data, l_conv_w, l_conv_b, r_conv_w, r_conv_b, tOff);
    fc_gemm<<<dim3(5, 16), 256>>>(feath, featl, l_fc_w, l_fc_b, r_fc_w, r_fc_b, both);
    conv2pool_kernel<<<dim3(NB, 2), 256>>>(conv2_w, conv2_b);
    l2_gemm<<<dim3(8, 8, L2S), 256>>>(yh, yl, l2_w, part);
    out_kernel<<<NB, 512>>>(part, hpart, l2_b, out_w, out_b, (float*)d_out, hidOut);
}

// round 14
// speedup vs baseline: 1.2453x; 1.2453x over previous
#include <cuda_runtime.h>
#include <cuda_bf16.h>

// ---------------------------------------------------------------------------
// ASLRNN3 sm_100a.  R11 structure (best: 151.2us) + conv2pool compute-once
// rework. Persistent-chain experiments (R6/R10/R13) conclusively closed:
// overlapped split-K chain on a side stream wins.
//  * only last frame feeds outs[-1]
//  * hidden recurrence: affine, i2h-independent -> homogeneous 501x501 power
//    via 5 squarings (512-pad), split-K=8 + reduce, on a side stream.
//  * all GEMMs: bf16 hi/lo split 3-MMA, fp32 accum, cp.async, ldmatrix frags.
// ---------------------------------------------------------------------------

#define NB 512
#define FEAT 304
#define HF 300
#define YK 9504
#define HID 500
#define HIDP 512
#define OUT 10
#define L2S 11         // l2 split-K  (9504 = 11*864, 864 = 27*32)
#define L2LEN 864
#define CHS 8          // chain split-K (512 = 8*64)
#define CHLEN 64

typedef __nv_bfloat16 bf;

// ---- scratch ----
__device__ bf g_feath[1024 * FEAT];
__device__ bf g_featl[1024 * FEAT];
__device__ float g_both[1024 * HF];
__device__ bf g_yh[NB * YK];
__device__ bf g_yl[NB * YK];
__device__ float g_part[L2S * NB * HID];
__device__ float g_cpart[CHS * HIDP * HIDP];
__device__ float g_hpart[CHS * NB * HID];
__device__ bf g_Wh [HIDP * HIDP];
__device__ bf g_Wl [HIDP * HIDP];
__device__ bf g_WTh[HIDP * HIDP];
__device__ bf g_WTl[HIDP * HIDP];
__device__ bf g_M0h[HIDP * HIDP];
__device__ bf g_M0l[HIDP * HIDP];
__device__ bf g_M0Th[HIDP * HIDP];
__device__ bf g_M0Tl[HIDP * HIDP];
__device__ bf g_M1h[HIDP * HIDP];
__device__ bf g_M1l[HIDP * HIDP];
__device__ bf g_M1Th[HIDP * HIDP];
__device__ bf g_M1Tl[HIDP * HIDP];
__device__ bf g_h0h[NB * HIDP];
__device__ bf g_h0l[NB * HIDP];
__device__ float g_hid[NB * HID];

#define MMA16816(c, a, b) asm volatile( \
    "mma.sync.aligned.m16n8k16.row.col.f32.bf16.bf16.f32 " \
    "{%0,%1,%2,%3},{%4,%5,%6,%7},{%8,%9},{%0,%1,%2,%3};\n" \
    : "+f"((c)[0]), "+f"((c)[1]), "+f"((c)[2]), "+f"((c)[3]) \
    : "r"((a)[0]), "r"((a)[1]), "r"((a)[2]), "r"((a)[3]), \
      "r"((b)[0]), "r"((b)[1]))

__device__ __forceinline__ void split_pair(float x, bf& h, bf& l) {
    h = __float2bfloat16(x);
    l = __float2bfloat16(x - __bfloat162float(h));
}
__device__ __forceinline__ void cp16(unsigned dst, const void* src) {
    asm volatile("cp.async.ca.shared.global [%0], [%1], 16;\n" :: "r"(dst), "l"(src));
}
#define CP_COMMIT asm volatile("cp.async.commit_group;\n")

#define SA 40
#define ARRE (64 * SA)

__device__ __forceinline__ void ldsm4(unsigned addr, unsigned* r) {
    asm volatile("ldmatrix.sync.aligned.m8n8.x4.shared.b16 {%0,%1,%2,%3}, [%4];"
        : "=r"(r[0]), "=r"(r[1]), "=r"(r[2]), "=r"(r[3]) : "r"(addr));
}

// hi/lo 3-MMA over NS 16-k-steps using ldmatrix fragment loads.
template<int ST, int ARR, int NS>
__device__ __forceinline__ void stage_mma_u(unsigned base, int wm, int wn,
                                            int lane, float acc[2][2][4])
{
    constexpr unsigned AB = ARR * 2;
    const int arow = lane & 15;
    const int acol = (lane >> 4) * 8;
    const int bg   = lane >> 3;
    const int brow = (bg >> 1) * 8 + (lane & 7);
    const int bcol = (bg & 1) * 8;
    #pragma unroll
    for (int s = 0; s < NS; ++s) {
        const int kb = s * 16;
        unsigned a_h[2][4], a_l[2][4], b_h[4], b_l[4];
        #pragma unroll
        for (int mt = 0; mt < 2; ++mt) {
            const unsigned ao = (unsigned)(((wm + mt * 16 + arow) * ST + kb + acol) * 2);
            ldsm4(base + ao,      a_h[mt]);
            ldsm4(base + AB + ao, a_l[mt]);
        }
        const unsigned bo = (unsigned)(((wn + brow) * ST + kb + bcol) * 2);
        ldsm4(base + 2 * AB + bo, b_h);
        ldsm4(base + 3 * AB + bo, b_l);
        #pragma unroll
        for (int mt = 0; mt < 2; ++mt)
            #pragma unroll
            for (int nt = 0; nt < 2; ++nt) {
                MMA16816(acc[mt][nt], a_h[mt], b_h + nt * 2);
                MMA16816(acc[mt][nt], a_h[mt], b_l + nt * 2);
                MMA16816(acc[mt][nt], a_l[mt], b_h + nt * 2);
            }
    }
}

// ---------------------------------------------------------------------------
// pp_gemm: pair A, pair B, split-K -> fp32 partials (chain + hidden GEMMs)
// ---------------------------------------------------------------------------
__global__ __launch_bounds__(256)
void pp_gemm(int M, int N, int K,
             const bf* __restrict__ Agh, const bf* __restrict__ Agl, int lda,
             const bf* __restrict__ Bgh, const bf* __restrict__ Bgl, int ldb,
             float* __restrict__ C, int ldc, int splitLen)
{
    __shared__ __align__(16) bf sm[2 * 4 * ARRE];
    const unsigned smb = (unsigned)__cvta_generic_to_shared(sm);
    constexpr unsigned ARRB = ARRE * 2;
    constexpr unsigned STAGEB = 4 * ARRB;

    const int tid  = threadIdx.x;
    const int wid  = tid >> 5;
    const int lane = tid & 31;
    const int wm   = (wid >> 2) * 32;
    const int wn   = (wid & 3) * 16;
    const int lr   = lane >> 2;
    const int lc   = lane & 3;
    const int m0   = blockIdx.y * 64;
    const int n0   = blockIdx.x * 64;

    const int kbeg = blockIdx.z * splitLen;
    const int kend = min(K, kbeg + splitLen);
    C += (size_t)blockIdx.z * (size_t)M * (size_t)ldc;

    float acc[2][2][4] = {};
    const int ar = tid >> 2;
    const int ac = (tid & 3) * 8;

    auto issue = [&](int k0, int st) {
        const size_t ao = (size_t)(m0 + ar) * lda + k0 + ac;
        const size_t bo = (size_t)(n0 + ar) * ldb + k0 + ac;
        const unsigned d = smb + st * STAGEB + (unsigned)(ar * SA + ac) * 2;
        cp16(d,            Agh + ao);
        cp16(d + ARRB,     Agl + ao);
        cp16(d + 2 * ARRB, Bgh + bo);
        cp16(d + 3 * ARRB, Bgl + bo);
        CP_COMMIT;
    };

    const int nit = (kend - kbeg) / 32;
    issue(kbeg, 0);
    for (int i = 0; i < nit; ++i) {
        if (i + 1 < nit) {
            issue(kbeg + (i + 1) * 32, (i + 1) & 1);
            asm volatile("cp.async.wait_group 1;\n");
        } else {
            asm volatile("cp.async.wait_group 0;\n");
        }
        __syncthreads();
        stage_mma_u<SA, ARRE, 2>(smb + (i & 1) * STAGEB, wm, wn, lane, acc);
        __syncthreads();
    }

    #pragma unroll
    for (int mt = 0; mt < 2; ++mt)
        #pragma unroll
        for (int nt = 0; nt < 2; ++nt)
            #pragma unroll
            for (int rr = 0; rr < 2; ++rr) {
                const int r = m0 + wm + mt * 16 + lr + rr * 8;
                #pragma unroll
                for (int j = 0; j < 2; ++j) {
                    const int c = n0 + wn + nt * 8 + lc * 2 + j;
                    if (c < N) C[(size_t)r * ldc + c] = acc[mt][nt][rr * 2 + j];
                }
            }
}

// ---------------------------------------------------------------------------
// reduce CHS fp32 partials -> bf16 pair (+ optional transposed pair), 512x512
template<bool WRITET>
__global__ __launch_bounds__(256)
void reduce_split(const float* __restrict__ part,
                  bf* __restrict__ Dh, bf* __restrict__ Dl,
                  bf* __restrict__ DTh, bf* __restrict__ DTl)
{
    __shared__ bf th[32][33], tl[32][33];
    const int bx = blockIdx.x * 32, by = blockIdx.y * 32;
    const int x = threadIdx.x & 31;
    const int y0 = threadIdx.x >> 5;
    #pragma unroll
    for (int dy = 0; dy < 32; dy += 8) {
        const int r = by + y0 + dy, c = bx + x;
        const size_t idx = (size_t)r * HIDP + c;
        float v = part[idx];
        #pragma unroll
        for (int s = 1; s < CHS; ++s) v += part[(size_t)s * HIDP * HIDP + idx];
        bf h, l;
        split_pair(v, h, l);
        Dh[idx] = h; Dl[idx] = l;
        th[y0 + dy][x] = h; tl[y0 + dy][x] = l;
    }
    if (WRITET) {
        __syncthreads();
        #pragma unroll
        for (int dy = 0; dy < 32; dy += 8) {
            const int r = bx + y0 + dy, c = by + x;
            const size_t idx = (size_t)r * HIDP + c;
            DTh[idx] = th[x][y0 + dy];
            DTl[idx] = tl[x][y0 + dy];
        }
    }
}

// ---------------------------------------------------------------------------
// l2_gemm: pair A (cp.async), fp32 B (register-prefetch + split in staging),
// split-K -> fp32 partials. B is (N,K)=(500,9504) row-major fp32.
// ---------------------------------------------------------------------------
__global__ __launch_bounds__(256)
void l2_gemm(const bf* __restrict__ Agh, const bf* __restrict__ Agl,
             const float* __restrict__ Bf,
             float* __restrict__ C)
{
    __shared__ __align__(16) bf sm[2 * 4 * ARRE];
    const unsigned smb = (unsigned)__cvta_generic_to_shared(sm);
    constexpr unsigned ARRB = ARRE * 2;
    constexpr unsigned STAGEB = 4 * ARRB;

    const int tid  = threadIdx.x;
    const int wid  = tid >> 5;
    const int lane = tid & 31;
    const int wm   = (wid >> 2) * 32;
    const int wn   = (wid & 3) * 16;
    const int lr   = lane >> 2;
    const int lc   = lane & 3;
    const int m0   = blockIdx.y * 64;
    const int n0   = blockIdx.x * 64;
    const int kbeg = blockIdx.z * L2LEN;
    C += (size_t)blockIdx.z * (size_t)NB * (size_t)HID;

    float acc[2][2][4] = {};
    const int ar = tid >> 2;
    const int ac = (tid & 3) * 8;
    const bool bvalid = (n0 + ar) < HID;
    const float* brow = Bf + (size_t)(n0 + ar) * YK;

    float4 rB0, rB1;

    auto issueA = [&](int k0, int st) {
        const size_t ao = (size_t)(m0 + ar) * YK + k0 + ac;
        const unsigned d = smb + st * STAGEB + (unsigned)(ar * SA + ac) * 2;
        cp16(d,        Agh + ao);
        cp16(d + ARRB, Agl + ao);
        CP_COMMIT;
    };
    auto loadB = [&](int k0) {
        if (bvalid) {
            rB0 = *reinterpret_cast<const float4*>(brow + k0 + ac);
            rB1 = *reinterpret_cast<const float4*>(brow + k0 + ac + 4);
        } else {
            rB0 = make_float4(0.f, 0.f, 0.f, 0.f);
            rB1 = make_float4(0.f, 0.f, 0.f, 0.f);
        }
    };
    auto storeB = [&](int st) {
        bf* Bh = sm + st * 4 * ARRE + 2 * ARRE + ar * SA + ac;
        bf* Bl = Bh + ARRE;
        const float v[8] = { rB0.x, rB0.y, rB0.z, rB0.w, rB1.x, rB1.y, rB1.z, rB1.w };
        uint4 vh, vl;
        bf* hv = reinterpret_cast<bf*>(&vh);
        bf* lv = reinterpret_cast<bf*>(&vl);
        #pragma unroll
        for (int e = 0; e < 8; ++e) split_pair(v[e], hv[e], lv[e]);
        *reinterpret_cast<uint4*>(Bh) = vh;
        *reinterpret_cast<uint4*>(Bl) = vl;
    };

    constexpr int nit = L2LEN / 32;
    issueA(kbeg, 0);
    loadB(kbeg);
    for (int i = 0; i < nit; ++i) {
        if (i + 1 < nit) issueA(kbeg + (i + 1) * 32, (i + 1) & 1);
        storeB(i & 1);
        if (i + 1 < nit) asm volatile("cp.async.wait_group 1;\n");
        else             asm volatile("cp.async.wait_group 0;\n");
        __syncthreads();
        if (i + 1 < nit) loadB(kbeg + (i + 1) * 32);
        stage_mma_u<SA, ARRE, 2>(smb + (i & 1) * STAGEB, wm, wn, lane, acc);
        __syncthreads();
    }

    #pragma unroll
    for (int mt = 0; mt < 2; ++mt)
        #pragma unroll
        for (int nt = 0; nt < 2; ++nt)
            #pragma unroll
            for (int rr = 0; rr < 2; ++rr) {
                const int r = m0 + wm + mt * 16 + lr + rr * 8;
                #pragma unroll
                for (int j = 0; j < 2; ++j) {
                    const int c = n0 + wn + nt * 8 + lc * 2 + j;
                    if (c < HID) C[(size_t)r * HID + c] = acc[mt][nt][rr * 2 + j];
                }
            }
}

// ---------------------------------------------------------------------------
// fc GEMM with register-prefetch double buffering (fp32 dual weights).
#define FSA 24
#define FARRE (64 * FSA)
__global__ __launch_bounds__(256)
void fc_gemm(const bf* __restrict__ Agh, const bf* __restrict__ Agl,
             const float* __restrict__ Bf, const float* __restrict__ bias,
             const float* __restrict__ Bf2, const float* __restrict__ bias2,
             float* __restrict__ C)
{
    constexpr int BK = 16;
    __shared__ __align__(16) bf smf[4 * FARRE];
    const unsigned smbf = (unsigned)__cvta_generic_to_shared(smf);
    bf* Ah = smf;
    bf* Al = smf + FARRE;
    bf* Bh = smf + 2 * FARRE;
    bf* Bl = smf + 3 * FARRE;

    const int tid  = threadIdx.x;
    const int wid  = tid >> 5;
    const int lane = tid & 31;
    const int wm   = (wid >> 2) * 32;
    const int wn   = (wid & 3) * 16;
    const int lr   = lane >> 2;
    const int lc   = lane & 3;
    const int m0   = blockIdx.y * 64;
    const int n0   = blockIdx.x * 64;
    const int N = HF, K = FEAT;

    if (blockIdx.y >= (gridDim.y >> 1)) { Bf = Bf2; bias = bias2; }

    float acc[2][2][4] = {};
    const int ar = tid >> 2;
    const int ac = (tid & 3) * 4;

    uint2 rAh, rAl;
    float4 rB;

    auto loadT = [&](int k0) {
        const size_t aoff = (size_t)(m0 + ar) * K + k0 + ac;
        rAh = *reinterpret_cast<const uint2*>(Agh + aoff);
        rAl = *reinterpret_cast<const uint2*>(Agl + aoff);
        if (n0 + ar < N)
            rB = *reinterpret_cast<const float4*>(&Bf[(size_t)(n0 + ar) * K + k0 + ac]);
        else
            rB = make_float4(0.f, 0.f, 0.f, 0.f);
    };
    auto storeT = [&]() {
        *reinterpret_cast<uint2*>(Ah + ar * FSA + ac) = rAh;
        *reinterpret_cast<uint2*>(Al + ar * FSA + ac) = rAl;
        split_pair(rB.x, Bh[ar * FSA + ac + 0], Bl[ar * FSA + ac + 0]);
        split_pair(rB.y, Bh[ar * FSA + ac + 1], Bl[ar * FSA + ac + 1]);
        split_pair(rB.z, Bh[ar * FSA + ac + 2], Bl[ar * FSA + ac + 2]);
        split_pair(rB.w, Bh[ar * FSA + ac + 3], Bl[ar * FSA + ac + 3]);
    };

    loadT(0);
    for (int k0 = 0; k0 < K; k0 += BK) {
        storeT();
        __syncthreads();
        if (k0 + BK < K) loadT(k0 + BK);
        stage_mma_u<FSA, FARRE, 1>(smbf, wm, wn, lane, acc);
        __syncthreads();
    }

    #pragma unroll
    for (int mt = 0; mt < 2; ++mt)
        #pragma unroll
        for (int nt = 0; nt < 2; ++nt)
            #pragma unroll
            for (int rr = 0; rr < 2; ++rr) {
                const int r = m0 + wm + mt * 16 + lr + rr * 8;
                #pragma unroll
                for (int j = 0; j < 2; ++j) {
                    const int c = n0 + wn + nt * 8 + lc * 2 + j;
                    if (c < N)
                        C[(size_t)r * HF + c] = fmaxf(acc[mt][nt][rr * 2 + j] + bias[c], 0.f);
                }
            }
}

// ---------------------------------------------------------------------------
__global__ void pad_kernel(const float* __restrict__ W,
                           const float* __restrict__ b,
                           const float* __restrict__ h0)
{
    int idx = blockIdx.x * blockDim.x + threadIdx.x;
    if (idx >= HIDP * HIDP) return;
    int r = idx >> 9, c = idx & (HIDP - 1);
    float wv = 0.f;
    if (r < HID) {
        if (c < HID) wv = W[r * HID + c];
        else if (c == HID) wv = b[r];
    } else if (r == HID && c == HID) wv = 1.f;
    bf h, l;
    split_pair(wv, h, l);
    g_Wh[idx] = h;  g_Wl[idx] = l;
    g_WTh[c * HIDP + r] = h;  g_WTl[c * HIDP + r] = l;
    float hv = (c < HID) ? h0[r * HID + c] : (c == HID ? 1.f : 0.f);
    split_pair(hv, g_h0h[idx], g_h0l[idx]);
}

// hand branch: conv1d(k=2,2->16) + relu + pool2 -> feat pair
__global__ void hand_feat_kernel(const float* __restrict__ hd,
                                 const float* __restrict__ lcw, const float* __restrict__ lcb,
                                 const float* __restrict__ rcw, const float* __restrict__ rcb,
                                 int tOff)
{
    const int s    = blockIdx.x;
    const int n    = s & (NB - 1);
    const int hand = s >> 9;
    const float* x  = hd + tOff + n * 84 + hand * 42;
    const float* cw = hand ? rcw : lcw;
    const float* cb = hand ? rcb : lcb;

    __shared__ float xs[42];
    __shared__ float z[16 * 20];
    const int tid = threadIdx.x;
    if (tid < 42) xs[tid] = x[tid];
    __syncthreads();

    for (int idx = tid; idx < 320; idx += 128) {
        int o = idx / 20, j = idx % 20;
        float v = cb[o]
                + cw[o * 4 + 0] * xs[2 * j]
                + cw[o * 4 + 1] * xs[2 * j + 2]
                + cw[o * 4 + 2] * xs[2 * j + 1]
                + cw[o * 4 + 3] * xs[2 * j + 3];
        z[o * 20 + j] = fmaxf(v, 0.f);
    }
    __syncthreads();

    for (int idx = tid; idx < FEAT; idx += 128) {
        int o = idx / 19, j = idx % 19;
        float v = fmaxf(z[o * 20 + j], z[o * 20 + j + 1]);
        split_pair(v, g_feath[(size_t)s * FEAT + idx], g_featl[(size_t)s * FEAT + idx]);
    }
}

// conv2(k=2,2->32) + relu + pool3 -> y pair; 2 blocks per sample (16 ch each).
// Compute-once rework: each warp computes its channel's 299 conv outputs once
// into a private smem row, then pools 297 maxima (saves ~2.3x FMA).
__global__ __launch_bounds__(256)
void conv2pool_kernel(const float* __restrict__ w2, const float* __restrict__ b2)
{
    __shared__ float slo[HF], sro[HF], sw[128], sb[32];
    __shared__ float z[16 * 304];
    const int n    = blockIdx.x;
    const int half = blockIdx.y;
    const int tid  = threadIdx.x;
    const int wid  = tid >> 5;
    const int lane = tid & 31;
    for (int i = tid; i < HF; i += 256) {
        slo[i] = g_both[(size_t)n * HF + i];
        sro[i] = g_both[(size_t)(NB + n) * HF + i];
    }
    if (tid < 128) sw[tid] = w2[tid];
    if (tid < 32)  sb[tid] = b2[tid];
    __syncthreads();

    #pragma unroll
    for (int oo = 0; oo < 2; ++oo) {
        const int zo = oo * 8 + wid;          // 0..15, warp-private row
        const int o  = half * 16 + zo;        // global channel
        const float w00 = sw[o * 4 + 0], w01 = sw[o * 4 + 1];
        const float w10 = sw[o * 4 + 2], w11 = sw[o * 4 + 3];
        const float bb = sb[o];
        float* zr = z + zo * 304;
        for (int j = lane; j < 299; j += 32)
            zr[j] = bb + w00 * slo[j] + w01 * slo[j + 1]
                       + w10 * sro[j] + w11 * sro[j + 1];
        __syncwarp();
        const size_t obase = (size_t)n * YK + o * 297;
        for (int j = lane; j < 297; j += 32) {
            float v = fmaxf(fmaxf(zr[j], zr[j + 1]), fmaxf(zr[j + 2], 0.f));
            split_pair(v, g_yh[obase + j], g_yl[obase + j]);
        }
    }
}

// final: hidden = sum(hpart); i2h = sum(part)+l2b; out = relu((i2h+hidden)@ow^T+ob)
__global__ __launch_bounds__(512)
void out_kernel(const float* __restrict__ part,
                const float* __restrict__ hpart,
                const float* __restrict__ l2b,
                const float* __restrict__ ow,
                const float* __restrict__ ob,
                float* __restrict__ out,
                float* __restrict__ hidOut)
{
    __shared__ float val[HID];
    const int n   = blockIdx.x;
    const int tid = threadIdx.x;

    if (tid < HID) {
        const size_t o = (size_t)n * HID + tid;
        float hs = hpart[o];
        #pragma unroll
        for (int s = 1; s < CHS; ++s) hs += hpart[(size_t)s * NB * HID + o];
        float is = l2b[tid];
        #pragma unroll
        for (int s = 0; s < L2S; ++s) is += part[(size_t)s * NB * HID + o];
        hidOut[o] = hs;
        val[tid] = hs + is;
    }
    __syncthreads();

    if (tid < OUT * 32) {
        const int m    = tid >> 5;
        const int lane = tid & 31;
        const float* w = ow + (size_t)m * HID;
        float s = 0.f;
        for (int k = lane; k < HID; k += 32) s += val[k] * w[k];
        #pragma unroll
        for (int o = 16; o; o >>= 1) s += __shfl_down_sync(0xffffffffu, s, o);
        if (lane == 0) out[n * OUT + m] = fmaxf(s + ob[m], 0.f);
    }
}

// ---------------------------------------------------------------------------
static cudaStream_t s_side = nullptr;
static cudaEvent_t  s_evF  = nullptr;
static cudaEvent_t  s_evJ  = nullptr;

extern "C" void kernel_launch(void* const* d_in, const int* in_sizes, int n_in,
                              void* d_out, int out_size)
{
    if (!s_side) {
        cudaStreamCreateWithFlags(&s_side, cudaStreamNonBlocking);
        cudaEventCreateWithFlags(&s_evF, cudaEventDisableTiming);
        cudaEventCreateWithFlags(&s_evJ, cudaEventDisableTiming);
    }

    const float* hand_data = (const float*)d_in[0];
    const float* hidden    = (const float*)d_in[1];
    const float* l_conv_w  = (const float*)d_in[2];
    const float* l_conv_b  = (const float*)d_in[3];
    const float* l_fc_w    = (const float*)d_in[4];
    const float* l_fc_b    = (const float*)d_in[5];
    const float* r_conv_w  = (const float*)d_in[6];
    const float* r_conv_b  = (const float*)d_in[7];
    const float* r_fc_w    = (const float*)d_in[8];
    const float* r_fc_b    = (const float*)d_in[9];
    const float* conv2_w   = (const float*)d_in[10];
    const float* conv2_b   = (const float*)d_in[11];
    const float* l2_w      = (const float*)d_in[12];
    const float* l2_b      = (const float*)d_in[13];
    const float* h2h_w     = (const float*)d_in[14];
    const float* h2h_b     = (const float*)d_in[15];
    const float* out_w     = (const float*)d_in[16];
    const float* out_b     = (const float*)d_in[17];

    const int T    = in_sizes[0] / (NB * 84);
    const int tOff = (T - 1) * NB * 84;

    bf *feath, *featl, *yh, *yl;
    bf *Wh, *Wl, *WTh, *WTl, *M0h, *M0l, *M0Th, *M0Tl, *M1h, *M1l, *M1Th, *M1Tl;
    bf *h0h, *h0l;
    float *both, *part, *cpart, *hpart, *hid;
    cudaGetSymbolAddress((void**)&feath, g_feath);
    cudaGetSymbolAddress((void**)&featl, g_featl);
    cudaGetSymbolAddress((void**)&both,  g_both);
    cudaGetSymbolAddress((void**)&yh,    g_yh);
    cudaGetSymbolAddress((void**)&yl,    g_yl);
    cudaGetSymbolAddress((void**)&part,  g_part);
    cudaGetSymbolAddress((void**)&cpart, g_cpart);
    cudaGetSymbolAddress((void**)&hpart, g_hpart);
    cudaGetSymbolAddress((void**)&Wh,    g_Wh);
    cudaGetSymbolAddress((void**)&Wl,    g_Wl);
    cudaGetSymbolAddress((void**)&WTh,   g_WTh);
    cudaGetSymbolAddress((void**)&WTl,   g_WTl);
    cudaGetSymbolAddress((void**)&M0h,   g_M0h);
    cudaGetSymbolAddress((void**)&M0l,   g_M0l);
    cudaGetSymbolAddress((void**)&M0Th,  g_M0Th);
    cudaGetSymbolAddress((void**)&M0Tl,  g_M0Tl);
    cudaGetSymbolAddress((void**)&M1h,   g_M1h);
    cudaGetSymbolAddress((void**)&M1l,   g_M1l);
    cudaGetSymbolAddress((void**)&M1Th,  g_M1Th);
    cudaGetSymbolAddress((void**)&M1Tl,  g_M1Tl);
    cudaGetSymbolAddress((void**)&h0h,   g_h0h);
    cudaGetSymbolAddress((void**)&h0l,   g_h0l);
    cudaGetSymbolAddress((void**)&hid,   g_hid);

    float* hidOut = (out_size >= NB * OUT + NB * HID) ? ((float*)d_out) + NB * OUT : hid;

    // fork side stream off the main stream head
    cudaEventRecord(s_evF, 0);
    cudaStreamWaitEvent(s_side, s_evF, 0);

    // ---- side stream: pad -> 5x (split-K squaring + reduce) -> hidden partials
    pad_kernel<<<(HIDP * HIDP + 255) / 256, 256, 0, s_side>>>(h2h_w, h2h_b, hidden);
    {
        const bf *sh = Wh, *sl = Wl, *sth = WTh, *stl = WTl;
        bf* dh [5] = { M0h,  M1h,  M0h,  M1h,  M0h  };
        bf* dl [5] = { M0l,  M1l,  M0l,  M1l,  M0l  };
        bf* dth[5] = { M0Th, M1Th, M0Th, M1Th, M0Th };
        bf* dtl[5] = { M0Tl, M1Tl, M0Tl, M1Tl, M0Tl };
        for (int i = 0; i < 5; ++i) {
            pp_gemm<<<dim3(8, 8, CHS), 256, 0, s_side>>>(
                HIDP, HIDP, HIDP, sh, sl, HIDP, sth, stl, HIDP, cpart, HIDP, CHLEN);
            if (i < 4)
                reduce_split<true><<<dim3(16, 16), 256, 0, s_side>>>(
                    cpart, dh[i], dl[i], dth[i], dtl[i]);
            else
                reduce_split<false><<<dim3(16, 16), 256, 0, s_side>>>(
                    cpart, dh[i], dl[i], nullptr, nullptr);
            sh = dh[i]; sl = dl[i]; sth = dth[i]; stl = dtl[i];
        }
        // hidden partials = h0aug @ M32^T (bias via homogeneous column)
        pp_gemm<<<dim3(8, 8, CHS), 256, 0, s_side>>>(
            NB, HID, HIDP, h0h, h0l, HIDP, M0h, M0l, HIDP, hpart, HID, CHLEN);
    }
    cudaEventRecord(s_evJ, s_side);

    // ---- main stream: data front-end
    hand_feat_kernel<<<1024, 128>>>(hand_data, l_conv_w, l_conv_b, r_conv_w, r_conv_b, tOff);
    fc_gemm<<<dim3(5, 16), 256>>>(feath, featl, l_fc_w, l_fc_b, r_fc_w, r_fc_b, both);
    conv2pool_kernel<<<dim3(NB, 2), 256>>>(conv2_w, conv2_b);
    l2_gemm<<<dim3(8, 8, L2S), 256>>>(yh, yl, l2_w, part);

    // ---- join + final fused kernel
    cudaStreamWaitEvent(0, s_evJ, 0);
    out_kernel<<<NB, 512>>>(part, hpart, l2_b, out_w, out_b, (float*)d_out, hidOut);
}

// round 15
// speedup vs baseline: 1.2581x; 1.0103x over previous
#include <cuda_runtime.h>
#include <cuda_bf16.h>

// ---------------------------------------------------------------------------
// ASLRNN3 sm_100a.  R14 structure (151.3us) + (a) identical preferred smem
// carveout pinned on ALL kernels (avoid L1/SMEM reconfig drain between
// launches with 41KB vs 4KB footprints), (b) chain split-K 8->4 (halves
// reduce traffic; per-launch GEMM time measured insensitive to k-iters).
//  * only last frame feeds outs[-1]
//  * hidden recurrence: affine, i2h-independent -> homogeneous 501x501 power
//    via 5 squarings (512-pad), split-K + reduce, on a side stream.
//  * all GEMMs: bf16 hi/lo split 3-MMA, fp32 accum, cp.async, ldmatrix frags.
// ---------------------------------------------------------------------------

#define NB 512
#define FEAT 304
#define HF 300
#define YK 9504
#define HID 500
#define HIDP 512
#define OUT 10
#define L2S 11         // l2 split-K  (9504 = 11*864, 864 = 27*32)
#define L2LEN 864
#define CHS 4          // chain split-K (512 = 4*128)
#define CHLEN 128

typedef __nv_bfloat16 bf;

// ---- scratch ----
__device__ bf g_feath[1024 * FEAT];
__device__ bf g_featl[1024 * FEAT];
__device__ float g_both[1024 * HF];
__device__ bf g_yh[NB * YK];
__device__ bf g_yl[NB * YK];
__device__ float g_part[L2S * NB * HID];
__device__ float g_cpart[CHS * HIDP * HIDP];
__device__ float g_hpart[CHS * NB * HID];
__device__ bf g_Wh [HIDP * HIDP];
__device__ bf g_Wl [HIDP * HIDP];
__device__ bf g_WTh[HIDP * HIDP];
__device__ bf g_WTl[HIDP * HIDP];
__device__ bf g_M0h[HIDP * HIDP];
__device__ bf g_M0l[HIDP * HIDP];
__device__ bf g_M0Th[HIDP * HIDP];
__device__ bf g_M0Tl[HIDP * HIDP];
__device__ bf g_M1h[HIDP * HIDP];
__device__ bf g_M1l[HIDP * HIDP];
__device__ bf g_M1Th[HIDP * HIDP];
__device__ bf g_M1Tl[HIDP * HIDP];
__device__ bf g_h0h[NB * HIDP];
__device__ bf g_h0l[NB * HIDP];
__device__ float g_hid[NB * HID];

#define MMA16816(c, a, b) asm volatile( \
    "mma.sync.aligned.m16n8k16.row.col.f32.bf16.bf16.f32 " \
    "{%0,%1,%2,%3},{%4,%5,%6,%7},{%8,%9},{%0,%1,%2,%3};\n" \
    : "+f"((c)[0]), "+f"((c)[1]), "+f"((c)[2]), "+f"((c)[3]) \
    : "r"((a)[0]), "r"((a)[1]), "r"((a)[2]), "r"((a)[3]), \
      "r"((b)[0]), "r"((b)[1]))

__device__ __forceinline__ void split_pair(float x, bf& h, bf& l) {
    h = __float2bfloat16(x);
    l = __float2bfloat16(x - __bfloat162float(h));
}
__device__ __forceinline__ void cp16(unsigned dst, const void* src) {
    asm volatile("cp.async.ca.shared.global [%0], [%1], 16;\n" :: "r"(dst), "l"(src));
}
#define CP_COMMIT asm volatile("cp.async.commit_group;\n")

#define SA 40
#define ARRE (64 * SA)

__device__ __forceinline__ void ldsm4(unsigned addr, unsigned* r) {
    asm volatile("ldmatrix.sync.aligned.m8n8.x4.shared.b16 {%0,%1,%2,%3}, [%4];"
        : "=r"(r[0]), "=r"(r[1]), "=r"(r[2]), "=r"(r[3]) : "r"(addr));
}

// hi/lo 3-MMA over NS 16-k-steps using ldmatrix fragment loads.
template<int ST, int ARR, int NS>
__device__ __forceinline__ void stage_mma_u(unsigned base, int wm, int wn,
                                            int lane, float acc[2][2][4])
{
    constexpr unsigned AB = ARR * 2;
    const int arow = lane & 15;
    const int acol = (lane >> 4) * 8;
    const int bg   = lane >> 3;
    const int brow = (bg >> 1) * 8 + (lane & 7);
    const int bcol = (bg & 1) * 8;
    #pragma unroll
    for (int s = 0; s < NS; ++s) {
        const int kb = s * 16;
        unsigned a_h[2][4], a_l[2][4], b_h[4], b_l[4];
        #pragma unroll
        for (int mt = 0; mt < 2; ++mt) {
            const unsigned ao = (unsigned)(((wm + mt * 16 + arow) * ST + kb + acol) * 2);
            ldsm4(base + ao,      a_h[mt]);
            ldsm4(base + AB + ao, a_l[mt]);
        }
        const unsigned bo = (unsigned)(((wn + brow) * ST + kb + bcol) * 2);
        ldsm4(base + 2 * AB + bo, b_h);
        ldsm4(base + 3 * AB + bo, b_l);
        #pragma unroll
        for (int mt = 0; mt < 2; ++mt)
            #pragma unroll
            for (int nt = 0; nt < 2; ++nt) {
                MMA16816(acc[mt][nt], a_h[mt], b_h + nt * 2);
                MMA16816(acc[mt][nt], a_h[mt], b_l + nt * 2);
                MMA16816(acc[mt][nt], a_l[mt], b_h + nt * 2);
            }
    }
}

// ---------------------------------------------------------------------------
// pp_gemm: pair A, pair B, split-K -> fp32 partials (chain + hidden GEMMs)
// ---------------------------------------------------------------------------
__global__ __launch_bounds__(256)
void pp_gemm(int M, int N, int K,
             const bf* __restrict__ Agh, const bf* __restrict__ Agl, int lda,
             const bf* __restrict__ Bgh, const bf* __restrict__ Bgl, int ldb,
             float* __restrict__ C, int ldc, int splitLen)
{
    __shared__ __align__(16) bf sm[2 * 4 * ARRE];
    const unsigned smb = (unsigned)__cvta_generic_to_shared(sm);
    constexpr unsigned ARRB = ARRE * 2;
    constexpr unsigned STAGEB = 4 * ARRB;

    const int tid  = threadIdx.x;
    const int wid  = tid >> 5;
    const int lane = tid & 31;
    const int wm   = (wid >> 2) * 32;
    const int wn   = (wid & 3) * 16;
    const int lr   = lane >> 2;
    const int lc   = lane & 3;
    const int m0   = blockIdx.y * 64;
    const int n0   = blockIdx.x * 64;

    const int kbeg = blockIdx.z * splitLen;
    const int kend = min(K, kbeg + splitLen);
    C += (size_t)blockIdx.z * (size_t)M * (size_t)ldc;

    float acc[2][2][4] = {};
    const int ar = tid >> 2;
    const int ac = (tid & 3) * 8;

    auto issue = [&](int k0, int st) {
        const size_t ao = (size_t)(m0 + ar) * lda + k0 + ac;
        const size_t bo = (size_t)(n0 + ar) * ldb + k0 + ac;
        const unsigned d = smb + st * STAGEB + (unsigned)(ar * SA + ac) * 2;
        cp16(d,            Agh + ao);
        cp16(d + ARRB,     Agl + ao);
        cp16(d + 2 * ARRB, Bgh + bo);
        cp16(d + 3 * ARRB, Bgl + bo);
        CP_COMMIT;
    };

    const int nit = (kend - kbeg) / 32;
    issue(kbeg, 0);
    for (int i = 0; i < nit; ++i) {
        if (i + 1 < nit) {
            issue(kbeg + (i + 1) * 32, (i + 1) & 1);
            asm volatile("cp.async.wait_group 1;\n");
        } else {
            asm volatile("cp.async.wait_group 0;\n");
        }
        __syncthreads();
        stage_mma_u<SA, ARRE, 2>(smb + (i & 1) * STAGEB, wm, wn, lane, acc);
        __syncthreads();
    }

    #pragma unroll
    for (int mt = 0; mt < 2; ++mt)
        #pragma unroll
        for (int nt = 0; nt < 2; ++nt)
            #pragma unroll
            for (int rr = 0; rr < 2; ++rr) {
                const int r = m0 + wm + mt * 16 + lr + rr * 8;
                #pragma unroll
                for (int j = 0; j < 2; ++j) {
                    const int c = n0 + wn + nt * 8 + lc * 2 + j;
                    if (c < N) C[(size_t)r * ldc + c] = acc[mt][nt][rr * 2 + j];
                }
            }
}

// ---------------------------------------------------------------------------
// reduce CHS fp32 partials -> bf16 pair (+ optional transposed pair), 512x512
template<bool WRITET>
__global__ __launch_bounds__(256)
void reduce_split(const float* __restrict__ part,
                  bf* __restrict__ Dh, bf* __restrict__ Dl,
                  bf* __restrict__ DTh, bf* __restrict__ DTl)
{
    __shared__ bf th[32][33], tl[32][33];
    const int bx = blockIdx.x * 32, by = blockIdx.y * 32;
    const int x = threadIdx.x & 31;
    const int y0 = threadIdx.x >> 5;
    #pragma unroll
    for (int dy = 0; dy < 32; dy += 8) {
        const int r = by + y0 + dy, c = bx + x;
        const size_t idx = (size_t)r * HIDP + c;
        float v = part[idx];
        #pragma unroll
        for (int s = 1; s < CHS; ++s) v += part[(size_t)s * HIDP * HIDP + idx];
        bf h, l;
        split_pair(v, h, l);
        Dh[idx] = h; Dl[idx] = l;
        th[y0 + dy][x] = h; tl[y0 + dy][x] = l;
    }
    if (WRITET) {
        __syncthreads();
        #pragma unroll
        for (int dy = 0; dy < 32; dy += 8) {
            const int r = bx + y0 + dy, c = by + x;
            const size_t idx = (size_t)r * HIDP + c;
            DTh[idx] = th[x][y0 + dy];
            DTl[idx] = tl[x][y0 + dy];
        }
    }
}

// ---------------------------------------------------------------------------
// l2_gemm: pair A (cp.async), fp32 B (register-prefetch + split in staging),
// split-K -> fp32 partials. B is (N,K)=(500,9504) row-major fp32.
// ---------------------------------------------------------------------------
__global__ __launch_bounds__(256)
void l2_gemm(const bf* __restrict__ Agh, const bf* __restrict__ Agl,
             const float* __restrict__ Bf,
             float* __restrict__ C)
{
    __shared__ __align__(16) bf sm[2 * 4 * ARRE];
    const unsigned smb = (unsigned)__cvta_generic_to_shared(sm);
    constexpr unsigned ARRB = ARRE * 2;
    constexpr unsigned STAGEB = 4 * ARRB;

    const int tid  = threadIdx.x;
    const int wid  = tid >> 5;
    const int lane = tid & 31;
    const int wm   = (wid >> 2) * 32;
    const int wn   = (wid & 3) * 16;
    const int lr   = lane >> 2;
    const int lc   = lane & 3;
    const int m0   = blockIdx.y * 64;
    const int n0   = blockIdx.x * 64;
    const int kbeg = blockIdx.z * L2LEN;
    C += (size_t)blockIdx.z * (size_t)NB * (size_t)HID;

    float acc[2][2][4] = {};
    const int ar = tid >> 2;
    const int ac = (tid & 3) * 8;
    const bool bvalid = (n0 + ar) < HID;
    const float* brow = Bf + (size_t)(n0 + ar) * YK;

    float4 rB0, rB1;

    auto issueA = [&](int k0, int st) {
        const size_t ao = (size_t)(m0 + ar) * YK + k0 + ac;
        const unsigned d = smb + st * STAGEB + (unsigned)(ar * SA + ac) * 2;
        cp16(d,        Agh + ao);
        cp16(d + ARRB, Agl + ao);
        CP_COMMIT;
    };
    auto loadB = [&](int k0) {
        if (bvalid) {
            rB0 = *reinterpret_cast<const float4*>(brow + k0 + ac);
            rB1 = *reinterpret_cast<const float4*>(brow + k0 + ac + 4);
        } else {
            rB0 = make_float4(0.f, 0.f, 0.f, 0.f);
            rB1 = make_float4(0.f, 0.f, 0.f, 0.f);
        }
    };
    auto storeB = [&](int st) {
        bf* Bh = sm + st * 4 * ARRE + 2 * ARRE + ar * SA + ac;
        bf* Bl = Bh + ARRE;
        const float v[8] = { rB0.x, rB0.y, rB0.z, rB0.w, rB1.x, rB1.y, rB1.z, rB1.w };
        uint4 vh, vl;
        bf* hv = reinterpret_cast<bf*>(&vh);
        bf* lv = reinterpret_cast<bf*>(&vl);
        #pragma unroll
        for (int e = 0; e < 8; ++e) split_pair(v[e], hv[e], lv[e]);
        *reinterpret_cast<uint4*>(Bh) = vh;
        *reinterpret_cast<uint4*>(Bl) = vl;
    };

    constexpr int nit = L2LEN / 32;
    issueA(kbeg, 0);
    loadB(kbeg);
    for (int i = 0; i < nit; ++i) {
        if (i + 1 < nit) issueA(kbeg + (i + 1) * 32, (i + 1) & 1);
        storeB(i & 1);
        if (i + 1 < nit) asm volatile("cp.async.wait_group 1;\n");
        else             asm volatile("cp.async.wait_group 0;\n");
        __syncthreads();
        if (i + 1 < nit) loadB(kbeg + (i + 1) * 32);
        stage_mma_u<SA, ARRE, 2>(smb + (i & 1) * STAGEB, wm, wn, lane, acc);
        __syncthreads();
    }

    #pragma unroll
    for (int mt = 0; mt < 2; ++mt)
        #pragma unroll
        for (int nt = 0; nt < 2; ++nt)
            #pragma unroll
            for (int rr = 0; rr < 2; ++rr) {
                const int r = m0 + wm + mt * 16 + lr + rr * 8;
                #pragma unroll
                for (int j = 0; j < 2; ++j) {
                    const int c = n0 + wn + nt * 8 + lc * 2 + j;
                    if (c < HID) C[(size_t)r * HID + c] = acc[mt][nt][rr * 2 + j];
                }
            }
}

// ---------------------------------------------------------------------------
// fc GEMM with register-prefetch double buffering (fp32 dual weights).
#define FSA 24
#define FARRE (64 * FSA)
__global__ __launch_bounds__(256)
void fc_gemm(const bf* __restrict__ Agh, const bf* __restrict__ Agl,
             const float* __restrict__ Bf, const float* __restrict__ bias,
             const float* __restrict__ Bf2, const float* __restrict__ bias2,
             float* __restrict__ C)
{
    constexpr int BK = 16;
    __shared__ __align__(16) bf smf[4 * FARRE];
    const unsigned smbf = (unsigned)__cvta_generic_to_shared(smf);
    bf* Ah = smf;
    bf* Al = smf + FARRE;
    bf* Bh = smf + 2 * FARRE;
    bf* Bl = smf + 3 * FARRE;

    const int tid  = threadIdx.x;
    const int wid  = tid >> 5;
    const int lane = tid & 31;
    const int wm   = (wid >> 2) * 32;
    const int wn   = (wid & 3) * 16;
    const int lr   = lane >> 2;
    const int lc   = lane & 3;
    const int m0   = blockIdx.y * 64;
    const int n0   = blockIdx.x * 64;
    const int N = HF, K = FEAT;

    if (blockIdx.y >= (gridDim.y >> 1)) { Bf = Bf2; bias = bias2; }

    float acc[2][2][4] = {};
    const int ar = tid >> 2;
    const int ac = (tid & 3) * 4;

    uint2 rAh, rAl;
    float4 rB;

    auto loadT = [&](int k0) {
        const size_t aoff = (size_t)(m0 + ar) * K + k0 + ac;
        rAh = *reinterpret_cast<const uint2*>(Agh + aoff);
        rAl = *reinterpret_cast<const uint2*>(Agl + aoff);
        if (n0 + ar < N)
            rB = *reinterpret_cast<const float4*>(&Bf[(size_t)(n0 + ar) * K + k0 + ac]);
        else
            rB = make_float4(0.f, 0.f, 0.f, 0.f);
    };
    auto storeT = [&]() {
        *reinterpret_cast<uint2*>(Ah + ar * FSA + ac) = rAh;
        *reinterpret_cast<uint2*>(Al + ar * FSA + ac) = rAl;
        split_pair(rB.x, Bh[ar * FSA + ac + 0], Bl[ar * FSA + ac + 0]);
        split_pair(rB.y, Bh[ar * FSA + ac + 1], Bl[ar * FSA + ac + 1]);
        split_pair(rB.z, Bh[ar * FSA + ac + 2], Bl[ar * FSA + ac + 2]);
        split_pair(rB.w, Bh[ar * FSA + ac + 3], Bl[ar * FSA + ac + 3]);
    };

    loadT(0);
    for (int k0 = 0; k0 < K; k0 += BK) {
        storeT();
        __syncthreads();
        if (k0 + BK < K) loadT(k0 + BK);
        stage_mma_u<FSA, FARRE, 1>(smbf, wm, wn, lane, acc);
        __syncthreads();
    }

    #pragma unroll
    for (int mt = 0; mt < 2; ++mt)
        #pragma unroll
        for (int nt = 0; nt < 2; ++nt)
            #pragma unroll
            for (int rr = 0; rr < 2; ++rr) {
                const int r = m0 + wm + mt * 16 + lr + rr * 8;
                #pragma unroll
                for (int j = 0; j < 2; ++j) {
                    const int c = n0 + wn + nt * 8 + lc * 2 + j;
                    if (c < N)
                        C[(size_t)r * HF + c] = fmaxf(acc[mt][nt][rr * 2 + j] + bias[c], 0.f);
                }
            }
}

// ---------------------------------------------------------------------------
__global__ void pad_kernel(const float* __restrict__ W,
                           const float* __restrict__ b,
                           const float* __restrict__ h0)
{
    int idx = blockIdx.x * blockDim.x + threadIdx.x;
    if (idx >= HIDP * HIDP) return;
    int r = idx >> 9, c = idx & (HIDP - 1);
    float wv = 0.f;
    if (r < HID) {
        if (c < HID) wv = W[r * HID + c];
        else if (c == HID) wv = b[r];
    } else if (r == HID && c == HID) wv = 1.f;
    bf h, l;
    split_pair(wv, h, l);
    g_Wh[idx] = h;  g_Wl[idx] = l;
    g_WTh[c * HIDP + r] = h;  g_WTl[c * HIDP + r] = l;
    float hv = (c < HID) ? h0[r * HID + c] : (c == HID ? 1.f : 0.f);
    split_pair(hv, g_h0h[idx], g_h0l[idx]);
}

// hand branch: conv1d(k=2,2->16) + relu + pool2 -> feat pair
__global__ void hand_feat_kernel(const float* __restrict__ hd,
                                 const float* __restrict__ lcw, const float* __restrict__ lcb,
                                 const float* __restrict__ rcw, const float* __restrict__ rcb,
                                 int tOff)
{
    const int s    = blockIdx.x;
    const int n    = s & (NB - 1);
    const int hand = s >> 9;
    const float* x  = hd + tOff + n * 84 + hand * 42;
    const float* cw = hand ? rcw : lcw;
    const float* cb = hand ? rcb : lcb;

    __shared__ float xs[42];
    __shared__ float z[16 * 20];
    const int tid = threadIdx.x;
    if (tid < 42) xs[tid] = x[tid];
    __syncthreads();

    for (int idx = tid; idx < 320; idx += 128) {
        int o = idx / 20, j = idx % 20;
        float v = cb[o]
                + cw[o * 4 + 0] * xs[2 * j]
                + cw[o * 4 + 1] * xs[2 * j + 2]
                + cw[o * 4 + 2] * xs[2 * j + 1]
                + cw[o * 4 + 3] * xs[2 * j + 3];
        z[o * 20 + j] = fmaxf(v, 0.f);
    }
    __syncthreads();

    for (int idx = tid; idx < FEAT; idx += 128) {
        int o = idx / 19, j = idx % 19;
        float v = fmaxf(z[o * 20 + j], z[o * 20 + j + 1]);
        split_pair(v, g_feath[(size_t)s * FEAT + idx], g_featl[(size_t)s * FEAT + idx]);
    }
}

// conv2(k=2,2->32) + relu + pool3 -> y pair; 2 blocks per sample (16 ch each).
// Compute-once: each warp computes its channel's 299 conv outputs once into a
// private smem row, then pools 297 maxima.
__global__ __launch_bounds__(256)
void conv2pool_kernel(const float* __restrict__ w2, const float* __restrict__ b2)
{
    __shared__ float slo[HF], sro[HF], sw[128], sb[32];
    __shared__ float z[16 * 304];
    const int n    = blockIdx.x;
    const int half = blockIdx.y;
    const int tid  = threadIdx.x;
    const int wid  = tid >> 5;
    const int lane = tid & 31;
    for (int i = tid; i < HF; i += 256) {
        slo[i] = g_both[(size_t)n * HF + i];
        sro[i] = g_both[(size_t)(NB + n) * HF + i];
    }
    if (tid < 128) sw[tid] = w2[tid];
    if (tid < 32)  sb[tid] = b2[tid];
    __syncthreads();

    #pragma unroll
    for (int oo = 0; oo < 2; ++oo) {
        const int zo = oo * 8 + wid;
        const int o  = half * 16 + zo;
        const float w00 = sw[o * 4 + 0], w01 = sw[o * 4 + 1];
        const float w10 = sw[o * 4 + 2], w11 = sw[o * 4 + 3];
        const float bb = sb[o];
        float* zr = z + zo * 304;
        for (int j = lane; j < 299; j += 32)
            zr[j] = bb + w00 * slo[j] + w01 * slo[j + 1]
                       + w10 * sro[j] + w11 * sro[j + 1];
        __syncwarp();
        const size_t obase = (size_t)n * YK + o * 297;
        for (int j = lane; j < 297; j += 32) {
            float v = fmaxf(fmaxf(zr[j], zr[j + 1]), fmaxf(zr[j + 2], 0.f));
            split_pair(v, g_yh[obase + j], g_yl[obase + j]);
        }
    }
}

// final: hidden = sum(hpart); i2h = sum(part)+l2b; out = relu((i2h+hidden)@ow^T+ob)
__global__ __launch_bounds__(512)
void out_kernel(const float* __restrict__ part,
                const float* __restrict__ hpart,
                const float* __restrict__ l2b,
                const float* __restrict__ ow,
                const float* __restrict__ ob,
                float* __restrict__ out,
                float* __restrict__ hidOut)
{
    __shared__ float val[HID];
    const int n   = blockIdx.x;
    const int tid = threadIdx.x;

    if (tid < HID) {
        const size_t o = (size_t)n * HID + tid;
        float hs = hpart[o];
        #pragma unroll
        for (int s = 1; s < CHS; ++s) hs += hpart[(size_t)s * NB * HID + o];
        float is = l2b[tid];
        #pragma unroll
        for (int s = 0; s < L2S; ++s) is += part[(size_t)s * NB * HID + o];
        hidOut[o] = hs;
        val[tid] = hs + is;
    }
    __syncthreads();

    if (tid < OUT * 32) {
        const int m    = tid >> 5;
        const int lane = tid & 31;
        const float* w = ow + (size_t)m * HID;
        float s = 0.f;
        for (int k = lane; k < HID; k += 32) s += val[k] * w[k];
        #pragma unroll
        for (int o = 16; o; o >>= 1) s += __shfl_down_sync(0xffffffffu, s, o);
        if (lane == 0) out[n * OUT + m] = fmaxf(s + ob[m], 0.f);
    }
}

// ---------------------------------------------------------------------------
static cudaStream_t s_side = nullptr;
static cudaEvent_t  s_evF  = nullptr;
static cudaEvent_t  s_evJ  = nullptr;

extern "C" void kernel_launch(void* const* d_in, const int* in_sizes, int n_in,
                              void* d_out, int out_size)
{
    if (!s_side) {
        cudaStreamCreateWithFlags(&s_side, cudaStreamNonBlocking);
        cudaEventCreateWithFlags(&s_evF, cudaEventDisableTiming);
        cudaEventCreateWithFlags(&s_evJ, cudaEventDisableTiming);
        // Pin an identical preferred smem carveout on EVERY kernel so the
        // driver never drains SMs to reconfigure L1/SMEM between launches.
        cudaFuncSetAttribute(pp_gemm, cudaFuncAttributePreferredSharedMemoryCarveout,
                             cudaSharedmemCarveoutMaxShared);
        cudaFuncSetAttribute(l2_gemm, cudaFuncAttributePreferredSharedMemoryCarveout,
                             cudaSharedmemCarveoutMaxShared);
        cudaFuncSetAttribute(fc_gemm, cudaFuncAttributePreferredSharedMemoryCarveout,
                             cudaSharedmemCarveoutMaxShared);
        cudaFuncSetAttribute(reduce_split<true>, cudaFuncAttributePreferredSharedMemoryCarveout,
                             cudaSharedmemCarveoutMaxShared);
        cudaFuncSetAttribute(reduce_split<false>, cudaFuncAttributePreferredSharedMemoryCarveout,
                             cudaSharedmemCarveoutMaxShared);
        cudaFuncSetAttribute(pad_kernel, cudaFuncAttributePreferredSharedMemoryCarveout,
                             cudaSharedmemCarveoutMaxShared);
        cudaFuncSetAttribute(hand_feat_kernel, cudaFuncAttributePreferredSharedMemoryCarveout,
                             cudaSharedmemCarveoutMaxShared);
        cudaFuncSetAttribute(conv2pool_kernel, cudaFuncAttributePreferredSharedMemoryCarveout,
                             cudaSharedmemCarveoutMaxShared);
        cudaFuncSetAttribute(out_kernel, cudaFuncAttributePreferredSharedMemoryCarveout,
                             cudaSharedmemCarveoutMaxShared);
    }

    const float* hand_data = (const float*)d_in[0];
    const float* hidden    = (const float*)d_in[1];
    const float* l_conv_w  = (const float*)d_in[2];
    const float* l_conv_b  = (const float*)d_in[3];
    const float* l_fc_w    = (const float*)d_in[4];
    const float* l_fc_b    = (const float*)d_in[5];
    const float* r_conv_w  = (const float*)d_in[6];
    const float* r_conv_b  = (const float*)d_in[7];
    const float* r_fc_w    = (const float*)d_in[8];
    const float* r_fc_b    = (const float*)d_in[9];
    const float* conv2_w   = (const float*)d_in[10];
    const float* conv2_b   = (const float*)d_in[11];
    const float* l2_w      = (const float*)d_in[12];
    const float* l2_b      = (const float*)d_in[13];
    const float* h2h_w     = (const float*)d_in[14];
    const float* h2h_b     = (const float*)d_in[15];
    const float* out_w     = (const float*)d_in[16];
    const float* out_b     = (const float*)d_in[17];

    const int T    = in_sizes[0] / (NB * 84);
    const int tOff = (T - 1) * NB * 84;

    bf *feath, *featl, *yh, *yl;
    bf *Wh, *Wl, *WTh, *WTl, *M0h, *M0l, *M0Th, *M0Tl, *M1h, *M1l, *M1Th, *M1Tl;
    bf *h0h, *h0l;
    float *both, *part, *cpart, *hpart, *hid;
    cudaGetSymbolAddress((void**)&feath, g_feath);
    cudaGetSymbolAddress((void**)&featl, g_featl);
    cudaGetSymbolAddress((void**)&both,  g_both);
    cudaGetSymbolAddress((void**)&yh,    g_yh);
    cudaGetSymbolAddress((void**)&yl,    g_yl);
    cudaGetSymbolAddress((void**)&part,  g_part);
    cudaGetSymbolAddress((void**)&cpart, g_cpart);
    cudaGetSymbolAddress((void**)&hpart, g_hpart);
    cudaGetSymbolAddress((void**)&Wh,    g_Wh);
    cudaGetSymbolAddress((void**)&Wl,    g_Wl);
    cudaGetSymbolAddress((void**)&WTh,   g_WTh);
    cudaGetSymbolAddress((void**)&WTl,   g_WTl);
    cudaGetSymbolAddress((void**)&M0h,   g_M0h);
    cudaGetSymbolAddress((void**)&M0l,   g_M0l);
    cudaGetSymbolAddress((void**)&M0Th,  g_M0Th);
    cudaGetSymbolAddress((void**)&M0Tl,  g_M0Tl);
    cudaGetSymbolAddress((void**)&M1h,   g_M1h);
    cudaGetSymbolAddress((void**)&M1l,   g_M1l);
    cudaGetSymbolAddress((void**)&M1Th,  g_M1Th);
    cudaGetSymbolAddress((void**)&M1Tl,  g_M1Tl);
    cudaGetSymbolAddress((void**)&h0h,   g_h0h);
    cudaGetSymbolAddress((void**)&h0l,   g_h0l);
    cudaGetSymbolAddress((void**)&hid,   g_hid);

    float* hidOut = (out_size >= NB * OUT + NB * HID) ? ((float*)d_out) + NB * OUT : hid;

    // fork side stream off the main stream head
    cudaEventRecord(s_evF, 0);
    cudaStreamWaitEvent(s_side, s_evF, 0);

    // ---- side stream: pad -> 5x (split-K squaring + reduce) -> hidden partials
    pad_kernel<<<(HIDP * HIDP + 255) / 256, 256, 0, s_side>>>(h2h_w, h2h_b, hidden);
    {
        const bf *sh = Wh, *sl = Wl, *sth = WTh, *stl = WTl;
        bf* dh [5] = { M0h,  M1h,  M0h,  M1h,  M0h  };
        bf* dl [5] = { M0l,  M1l,  M0l,  M1l,  M0l  };
        bf* dth[5] = { M0Th, M1Th, M0Th, M1Th, M0Th };
        bf* dtl[5] = { M0Tl, M1Tl, M0Tl, M1Tl, M0Tl };
        for (int i = 0; i < 5; ++i) {
            pp_gemm<<<dim3(8, 8, CHS), 256, 0, s_side>>>(
                HIDP, HIDP, HIDP, sh, sl, HIDP, sth, stl, HIDP, cpart, HIDP, CHLEN);
            if (i < 4)
                reduce_split<true><<<dim3(16, 16), 256, 0, s_side>>>(
                    cpart, dh[i], dl[i], dth[i], dtl[i]);
            else
                reduce_split<false><<<dim3(16, 16), 256, 0, s_side>>>(
                    cpart, dh[i], dl[i], nullptr, nullptr);
            sh = dh[i]; sl = dl[i]; sth = dth[i]; stl = dtl[i];
        }
        // hidden partials = h0aug @ M32^T (bias via homogeneous column)
        pp_gemm<<<dim3(8, 8, CHS), 256, 0, s_side>>>(
            NB, HID, HIDP, h0h, h0l, HIDP, M0h, M0l, HIDP, hpart, HID, CHLEN);
    }
    cudaEventRecord(s_evJ, s_side);

    // ---- main stream: data front-end
    hand_feat_kernel<<<1024, 128>>>(hand_data, l_conv_w, l_conv_b, r_conv_w, r_conv_b, tOff);
    fc_gemm<<<dim3(5, 16), 256>>>(feath, featl, l_fc_w, l_fc_b, r_fc_w, r_fc_b, both);
    conv2pool_kernel<<<dim3(NB, 2), 256>>>(conv2_w, conv2_b);
    l2_gemm<<<dim3(8, 8, L2S), 256>>>(yh, yl, l2_w, part);

    // ---- join + final fused kernel
    cudaStreamWaitEvent(0, s_evJ, 0);
    out_kernel<<<NB, 512>>>(part, hpart, l2_b, out_w, out_b, (float*)d_out, hidOut);
}

// round 16
// speedup vs baseline: 1.2800x; 1.0174x over previous
#include <cuda_runtime.h>
#include <cuda_bf16.h>

// ---------------------------------------------------------------------------
// ASLRNN3 sm_100a.  R15 base (149.8us) +
//  (a) chain split-K 4->2: grid 128 <= 148 SMs -> ONE wave (no straggler 2x),
//      3-stage cp.async pipeline (60KB dynamic smem) hides per-iter latency.
//  (b) fc GEMM: FEAT padded to 320, BK=32 cp.async 2-stage (halves iters).
// Empirical law driving this: dur ~= ceil(blocks/148) * (1.2us + 0.95us*iters).
//  * only last frame feeds outs[-1]
//  * hidden recurrence: affine -> homogeneous 501x501 power, 5 squarings.
//  * all GEMMs: bf16 hi/lo split 3-MMA, fp32 accum, cp.async, ldmatrix frags.
// ---------------------------------------------------------------------------

#define NB 512
#define FEAT 304
#define FEATP 320      // padded K for fc (10 x 32)
#define HF 300
#define YK 9504
#define HID 500
#define HIDP 512
#define OUT 10
#define L2S 11         // l2 split-K  (9504 = 11*864)
#define L2LEN 864
#define CHS 2          // chain split-K (512 = 2*256) -> grid 128, one wave
#define CHLEN 256

typedef __nv_bfloat16 bf;

// ---- scratch ----
__device__ bf g_feath[1024 * FEATP];
__device__ bf g_featl[1024 * FEATP];
__device__ float g_both[1024 * HF];
__device__ bf g_yh[NB * YK];
__device__ bf g_yl[NB * YK];
__device__ float g_part[L2S * NB * HID];
__device__ float g_cpart[CHS * HIDP * HIDP];
__device__ float g_hpart[CHS * NB * HID];
__device__ bf g_Wh [HIDP * HIDP];
__device__ bf g_Wl [HIDP * HIDP];
__device__ bf g_WTh[HIDP * HIDP];
__device__ bf g_WTl[HIDP * HIDP];
__device__ bf g_M0h[HIDP * HIDP];
__device__ bf g_M0l[HIDP * HIDP];
__device__ bf g_M0Th[HIDP * HIDP];
__device__ bf g_M0Tl[HIDP * HIDP];
__device__ bf g_M1h[HIDP * HIDP];
__device__ bf g_M1l[HIDP * HIDP];
__device__ bf g_M1Th[HIDP * HIDP];
__device__ bf g_M1Tl[HIDP * HIDP];
__device__ bf g_h0h[NB * HIDP];
__device__ bf g_h0l[NB * HIDP];
__device__ float g_hid[NB * HID];

#define MMA16816(c, a, b) asm volatile( \
    "mma.sync.aligned.m16n8k16.row.col.f32.bf16.bf16.f32 " \
    "{%0,%1,%2,%3},{%4,%5,%6,%7},{%8,%9},{%0,%1,%2,%3};\n" \
    : "+f"((c)[0]), "+f"((c)[1]), "+f"((c)[2]), "+f"((c)[3]) \
    : "r"((a)[0]), "r"((a)[1]), "r"((a)[2]), "r"((a)[3]), \
      "r"((b)[0]), "r"((b)[1]))

__device__ __forceinline__ void split_pair(float x, bf& h, bf& l) {
    h = __float2bfloat16(x);
    l = __float2bfloat16(x - __bfloat162float(h));
}
__device__ __forceinline__ void cp16(unsigned dst, const void* src) {
    asm volatile("cp.async.ca.shared.global [%0], [%1], 16;\n" :: "r"(dst), "l"(src));
}
#define CP_COMMIT asm volatile("cp.async.commit_group;\n")

#define SA 40
#define ARRE (64 * SA)

__device__ __forceinline__ void ldsm4(unsigned addr, unsigned* r) {
    asm volatile("ldmatrix.sync.aligned.m8n8.x4.shared.b16 {%0,%1,%2,%3}, [%4];"
        : "=r"(r[0]), "=r"(r[1]), "=r"(r[2]), "=r"(r[3]) : "r"(addr));
}

// hi/lo 3-MMA over NS 16-k-steps using ldmatrix fragment loads.
template<int ST, int ARR, int NS>
__device__ __forceinline__ void stage_mma_u(unsigned base, int wm, int wn,
                                            int lane, float acc[2][2][4])
{
    constexpr unsigned AB = ARR * 2;
    const int arow = lane & 15;
    const int acol = (lane >> 4) * 8;
    const int bg   = lane >> 3;
    const int brow = (bg >> 1) * 8 + (lane & 7);
    const int bcol = (bg & 1) * 8;
    #pragma unroll
    for (int s = 0; s < NS; ++s) {
        const int kb = s * 16;
        unsigned a_h[2][4], a_l[2][4], b_h[4], b_l[4];
        #pragma unroll
        for (int mt = 0; mt < 2; ++mt) {
            const unsigned ao = (unsigned)(((wm + mt * 16 + arow) * ST + kb + acol) * 2);
            ldsm4(base + ao,      a_h[mt]);
            ldsm4(base + AB + ao, a_l[mt]);
        }
        const unsigned bo = (unsigned)(((wn + brow) * ST + kb + bcol) * 2);
        ldsm4(base + 2 * AB + bo, b_h);
        ldsm4(base + 3 * AB + bo, b_l);
        #pragma unroll
        for (int mt = 0; mt < 2; ++mt)
            #pragma unroll
            for (int nt = 0; nt < 2; ++nt) {
                MMA16816(acc[mt][nt], a_h[mt], b_h + nt * 2);
                MMA16816(acc[mt][nt], a_h[mt], b_l + nt * 2);
                MMA16816(acc[mt][nt], a_l[mt], b_h + nt * 2);
            }
    }
}

// ---------------------------------------------------------------------------
// pp_gemm: pair A, pair B, split-K -> fp32 partials. 3-stage cp.async
// pipeline in dynamic smem (60KB). K chunk % 32 == 0, >= 96.
// ---------------------------------------------------------------------------
__global__ __launch_bounds__(256)
void pp_gemm(int M, int N, int K,
             const bf* __restrict__ Agh, const bf* __restrict__ Agl, int lda,
             const bf* __restrict__ Bgh, const bf* __restrict__ Bgl, int ldb,
             float* __restrict__ C, int ldc, int splitLen)
{
    extern __shared__ __align__(16) bf smd[];
    const unsigned smb = (unsigned)__cvta_generic_to_shared(smd);
    constexpr unsigned ARRB = ARRE * 2;
    constexpr unsigned STAGEB = 4 * ARRB;

    const int tid  = threadIdx.x;
    const int wid  = tid >> 5;
    const int lane = tid & 31;
    const int wm   = (wid >> 2) * 32;
    const int wn   = (wid & 3) * 16;
    const int lr   = lane >> 2;
    const int lc   = lane & 3;
    const int m0   = blockIdx.y * 64;
    const int n0   = blockIdx.x * 64;

    const int kbeg = blockIdx.z * splitLen;
    const int kend = min(K, kbeg + splitLen);
    C += (size_t)blockIdx.z * (size_t)M * (size_t)ldc;

    float acc[2][2][4] = {};
    const int ar = tid >> 2;
    const int ac = (tid & 3) * 8;

    auto issue = [&](int k0, int st) {
        const size_t ao = (size_t)(m0 + ar) * lda + k0 + ac;
        const size_t bo = (size_t)(n0 + ar) * ldb + k0 + ac;
        const unsigned d = smb + st * STAGEB + (unsigned)(ar * SA + ac) * 2;
        cp16(d,            Agh + ao);
        cp16(d + ARRB,     Agl + ao);
        cp16(d + 2 * ARRB, Bgh + bo);
        cp16(d + 3 * ARRB, Bgl + bo);
        CP_COMMIT;
    };

    const int nit = (kend - kbeg) / 32;
    issue(kbeg, 0);
    issue(kbeg + 32, 1);
    int st = 0;
    for (int i = 0; i < nit; ++i) {
        if (i + 2 < nit) {
            issue(kbeg + (i + 2) * 32, (i + 2) % 3);
            asm volatile("cp.async.wait_group 2;\n");
        } else if (i + 1 < nit) {
            asm volatile("cp.async.wait_group 1;\n");
        } else {
            asm volatile("cp.async.wait_group 0;\n");
        }
        __syncthreads();
        stage_mma_u<SA, ARRE, 2>(smb + st * STAGEB, wm, wn, lane, acc);
        __syncthreads();
        if (++st == 3) st = 0;
    }

    #pragma unroll
    for (int mt = 0; mt < 2; ++mt)
        #pragma unroll
        for (int nt = 0; nt < 2; ++nt)
            #pragma unroll
            for (int rr = 0; rr < 2; ++rr) {
                const int r = m0 + wm + mt * 16 + lr + rr * 8;
                #pragma unroll
                for (int j = 0; j < 2; ++j) {
                    const int c = n0 + wn + nt * 8 + lc * 2 + j;
                    if (c < N) C[(size_t)r * ldc + c] = acc[mt][nt][rr * 2 + j];
                }
            }
}

// ---------------------------------------------------------------------------
// reduce CHS fp32 partials -> bf16 pair (+ optional transposed pair), 512x512
template<bool WRITET>
__global__ __launch_bounds__(256)
void reduce_split(const float* __restrict__ part,
                  bf* __restrict__ Dh, bf* __restrict__ Dl,
                  bf* __restrict__ DTh, bf* __restrict__ DTl)
{
    __shared__ bf th[32][33], tl[32][33];
    const int bx = blockIdx.x * 32, by = blockIdx.y * 32;
    const int x = threadIdx.x & 31;
    const int y0 = threadIdx.x >> 5;
    #pragma unroll
    for (int dy = 0; dy < 32; dy += 8) {
        const int r = by + y0 + dy, c = bx + x;
        const size_t idx = (size_t)r * HIDP + c;
        float v = part[idx];
        #pragma unroll
        for (int s = 1; s < CHS; ++s) v += part[(size_t)s * HIDP * HIDP + idx];
        bf h, l;
        split_pair(v, h, l);
        Dh[idx] = h; Dl[idx] = l;
        th[y0 + dy][x] = h; tl[y0 + dy][x] = l;
    }
    if (WRITET) {
        __syncthreads();
        #pragma unroll
        for (int dy = 0; dy < 32; dy += 8) {
            const int r = bx + y0 + dy, c = by + x;
            const size_t idx = (size_t)r * HIDP + c;
            DTh[idx] = th[x][y0 + dy];
            DTl[idx] = tl[x][y0 + dy];
        }
    }
}

// ---------------------------------------------------------------------------
// l2_gemm: pair A (cp.async), fp32 B (register-prefetch + split in staging),
// split-K -> fp32 partials. B is (N,K)=(500,9504) row-major fp32.
// ---------------------------------------------------------------------------
__global__ __launch_bounds__(256)
void l2_gemm(const bf* __restrict__ Agh, const bf* __restrict__ Agl,
             const float* __restrict__ Bf,
             float* __restrict__ C)
{
    __shared__ __align__(16) bf sm[2 * 4 * ARRE];
    const unsigned smb = (unsigned)__cvta_generic_to_shared(sm);
    constexpr unsigned ARRB = ARRE * 2;
    constexpr unsigned STAGEB = 4 * ARRB;

    const int tid  = threadIdx.x;
    const int wid  = tid >> 5;
    const int lane = tid & 31;
    const int wm   = (wid >> 2) * 32;
    const int wn   = (wid & 3) * 16;
    const int lr   = lane >> 2;
    const int lc   = lane & 3;
    const int m0   = blockIdx.y * 64;
    const int n0   = blockIdx.x * 64;
    const int kbeg = blockIdx.z * L2LEN;
    C += (size_t)blockIdx.z * (size_t)NB * (size_t)HID;

    float acc[2][2][4] = {};
    const int ar = tid >> 2;
    const int ac = (tid & 3) * 8;
    const bool bvalid = (n0 + ar) < HID;
    const float* brow = Bf + (size_t)(n0 + ar) * YK;

    float4 rB0, rB1;

    auto issueA = [&](int k0, int st) {
        const size_t ao = (size_t)(m0 + ar) * YK + k0 + ac;
        const unsigned d = smb + st * STAGEB + (unsigned)(ar * SA + ac) * 2;
        cp16(d,        Agh + ao);
        cp16(d + ARRB, Agl + ao);
        CP_COMMIT;
    };
    auto loadB = [&](int k0) {
        if (bvalid) {
            rB0 = *reinterpret_cast<const float4*>(brow + k0 + ac);
            rB1 = *reinterpret_cast<const float4*>(brow + k0 + ac + 4);
        } else {
            rB0 = make_float4(0.f, 0.f, 0.f, 0.f);
            rB1 = make_float4(0.f, 0.f, 0.f, 0.f);
        }
    };
    auto storeB = [&](int st) {
        bf* Bh = sm + st * 4 * ARRE + 2 * ARRE + ar * SA + ac;
        bf* Bl = Bh + ARRE;
        const float v[8] = { rB0.x, rB0.y, rB0.z, rB0.w, rB1.x, rB1.y, rB1.z, rB1.w };
        uint4 vh, vl;
        bf* hv = reinterpret_cast<bf*>(&vh);
        bf* lv = reinterpret_cast<bf*>(&vl);
        #pragma unroll
        for (int e = 0; e < 8; ++e) split_pair(v[e], hv[e], lv[e]);
        *reinterpret_cast<uint4*>(Bh) = vh;
        *reinterpret_cast<uint4*>(Bl) = vl;
    };

    constexpr int nit = L2LEN / 32;
    issueA(kbeg, 0);
    loadB(kbeg);
    for (int i = 0; i < nit; ++i) {
        if (i + 1 < nit) issueA(kbeg + (i + 1) * 32, (i + 1) & 1);
        storeB(i & 1);
        if (i + 1 < nit) asm volatile("cp.async.wait_group 1;\n");
        else             asm volatile("cp.async.wait_group 0;\n");
        __syncthreads();
        if (i + 1 < nit) loadB(kbeg + (i + 1) * 32);
        stage_mma_u<SA, ARRE, 2>(smb + (i & 1) * STAGEB, wm, wn, lane, acc);
        __syncthreads();
    }

    #pragma unroll
    for (int mt = 0; mt < 2; ++mt)
        #pragma unroll
        for (int nt = 0; nt < 2; ++nt)
            #pragma unroll
            for (int rr = 0; rr < 2; ++rr) {
                const int r = m0 + wm + mt * 16 + lr + rr * 8;
                #pragma unroll
                for (int j = 0; j < 2; ++j) {
                    const int c = n0 + wn + nt * 8 + lc * 2 + j;
                    if (c < HID) C[(size_t)r * HID + c] = acc[mt][nt][rr * 2 + j];
                }
            }
}

// ---------------------------------------------------------------------------
// fc GEMM: K=FEATP=320, BK=32, cp.async 2-stage A + register fp32 dual B.
__global__ __launch_bounds__(256)
void fc_gemm(const bf* __restrict__ Agh, const bf* __restrict__ Agl,
             const float* __restrict__ Bf, const float* __restrict__ bias,
             const float* __restrict__ Bf2, const float* __restrict__ bias2,
             float* __restrict__ C)
{
    __shared__ __align__(16) bf sm[2 * 4 * ARRE];
    const unsigned smb = (unsigned)__cvta_generic_to_shared(sm);
    constexpr unsigned ARRB = ARRE * 2;
    constexpr unsigned STAGEB = 4 * ARRB;

    const int tid  = threadIdx.x;
    const int wid  = tid >> 5;
    const int lane = tid & 31;
    const int wm   = (wid >> 2) * 32;
    const int wn   = (wid & 3) * 16;
    const int lr   = lane >> 2;
    const int lc   = lane & 3;
    const int m0   = blockIdx.y * 64;
    const int n0   = blockIdx.x * 64;
    const int N = HF;

    if (blockIdx.y >= (gridDim.y >> 1)) { Bf = Bf2; bias = bias2; }

    float acc[2][2][4] = {};
    const int ar = tid >> 2;
    const int ac = (tid & 3) * 8;
    const bool bvalid = (n0 + ar) < N;
    const float* brow = Bf + (size_t)(n0 + ar) * FEAT;   // weights are 304-wide!

    float4 rB0, rB1;

    auto issueA = [&](int k0, int st) {
        const size_t ao = (size_t)(m0 + ar) * FEATP + k0 + ac;
        const unsigned d = smb + st * STAGEB + (unsigned)(ar * SA + ac) * 2;
        cp16(d,        Agh + ao);
        cp16(d + ARRB, Agl + ao);
        CP_COMMIT;
    };
    auto loadB = [&](int k0) {
        rB0 = make_float4(0.f, 0.f, 0.f, 0.f);
        rB1 = make_float4(0.f, 0.f, 0.f, 0.f);
        if (bvalid) {
            const int k = k0 + ac;
            if (k + 3 < FEAT) rB0 = *reinterpret_cast<const float4*>(brow + k);
            if (k + 7 < FEAT) rB1 = *reinterpret_cast<const float4*>(brow + k + 4);
        }
    };
    auto storeB = [&](int st) {
        bf* Bh = sm + st * 4 * ARRE + 2 * ARRE + ar * SA + ac;
        bf* Bl = Bh + ARRE;
        const float v[8] = { rB0.x, rB0.y, rB0.z, rB0.w, rB1.x, rB1.y, rB1.z, rB1.w };
        uint4 vh, vl;
        bf* hv = reinterpret_cast<bf*>(&vh);
        bf* lv = reinterpret_cast<bf*>(&vl);
        #pragma unroll
        for (int e = 0; e < 8; ++e) split_pair(v[e], hv[e], lv[e]);
        *reinterpret_cast<uint4*>(Bh) = vh;
        *reinterpret_cast<uint4*>(Bl) = vl;
    };

    constexpr int nit = FEATP / 32;      // 10
    issueA(0, 0);
    loadB(0);
    for (int i = 0; i < nit; ++i) {
        if (i + 1 < nit) issueA((i + 1) * 32, (i + 1) & 1);
        storeB(i & 1);
        if (i + 1 < nit) asm volatile("cp.async.wait_group 1;\n");
        else             asm volatile("cp.async.wait_group 0;\n");
        __syncthreads();
        if (i + 1 < nit) loadB((i + 1) * 32);
        stage_mma_u<SA, ARRE, 2>(smb + (i & 1) * STAGEB, wm, wn, lane, acc);
        __syncthreads();
    }

    #pragma unroll
    for (int mt = 0; mt < 2; ++mt)
        #pragma unroll
        for (int nt = 0; nt < 2; ++nt)
            #pragma unroll
            for (int rr = 0; rr < 2; ++rr) {
                const int r = m0 + wm + mt * 16 + lr + rr * 8;
                #pragma unroll
                for (int j = 0; j < 2; ++j) {
                    const int c = n0 + wn + nt * 8 + lc * 2 + j;
                    if (c < N)
                        C[(size_t)r * HF + c] = fmaxf(acc[mt][nt][rr * 2 + j] + bias[c], 0.f);
                }
            }
}

// ---------------------------------------------------------------------------
__global__ void pad_kernel(const float* __restrict__ W,
                           const float* __restrict__ b,
                           const float* __restrict__ h0)
{
    int idx = blockIdx.x * blockDim.x + threadIdx.x;
    if (idx >= HIDP * HIDP) return;
    int r = idx >> 9, c = idx & (HIDP - 1);
    float wv = 0.f;
    if (r < HID) {
        if (c < HID) wv = W[r * HID + c];
        else if (c == HID) wv = b[r];
    } else if (r == HID && c == HID) wv = 1.f;
    bf h, l;
    split_pair(wv, h, l);
    g_Wh[idx] = h;  g_Wl[idx] = l;
    g_WTh[c * HIDP + r] = h;  g_WTl[c * HIDP + r] = l;
    float hv = (c < HID) ? h0[r * HID + c] : (c == HID ? 1.f : 0.f);
    split_pair(hv, g_h0h[idx], g_h0l[idx]);
}

// hand branch: conv1d(k=2,2->16) + relu + pool2 -> feat pair (320-padded)
__global__ void hand_feat_kernel(const float* __restrict__ hd,
                                 const float* __restrict__ lcw, const float* __restrict__ lcb,
                                 const float* __restrict__ rcw, const float* __restrict__ rcb,
                                 int tOff)
{
    const int s    = blockIdx.x;
    const int n    = s & (NB - 1);
    const int hand = s >> 9;
    const float* x  = hd + tOff + n * 84 + hand * 42;
    const float* cw = hand ? rcw : lcw;
    const float* cb = hand ? rcb : lcb;

    __shared__ float xs[42];
    __shared__ float z[16 * 20];
    const int tid = threadIdx.x;
    if (tid < 42) xs[tid] = x[tid];
    __syncthreads();

    for (int idx = tid; idx < 320; idx += 128) {
        int o = idx / 20, j = idx % 20;
        float v = cb[o]
                + cw[o * 4 + 0] * xs[2 * j]
                + cw[o * 4 + 1] * xs[2 * j + 2]
                + cw[o * 4 + 2] * xs[2 * j + 1]
                + cw[o * 4 + 3] * xs[2 * j + 3];
        z[o * 20 + j] = fmaxf(v, 0.f);
    }
    __syncthreads();

    for (int idx = tid; idx < FEATP; idx += 128) {
        float v = 0.f;
        if (idx < FEAT) {
            int o = idx / 19, j = idx % 19;
            v = fmaxf(z[o * 20 + j], z[o * 20 + j + 1]);
        }
        split_pair(v, g_feath[(size_t)s * FEATP + idx], g_featl[(size_t)s * FEATP + idx]);
    }
}

// conv2(k=2,2->32) + relu + pool3 -> y pair; 2 blocks per sample (16 ch each).
__global__ __launch_bounds__(256)
void conv2pool_kernel(const float* __restrict__ w2, const float* __restrict__ b2)
{
    __shared__ float slo[HF], sro[HF], sw[128], sb[32];
    __shared__ float z[16 * 304];
    const int n    = blockIdx.x;
    const int half = blockIdx.y;
    const int tid  = threadIdx.x;
    const int wid  = tid >> 5;
    const int lane = tid & 31;
    for (int i = tid; i < HF; i += 256) {
        slo[i] = g_both[(size_t)n * HF + i];
        sro[i] = g_both[(size_t)(NB + n) * HF + i];
    }
    if (tid < 128) sw[tid] = w2[tid];
    if (tid < 32)  sb[tid] = b2[tid];
    __syncthreads();

    #pragma unroll
    for (int oo = 0; oo < 2; ++oo) {
        const int zo = oo * 8 + wid;
        const int o  = half * 16 + zo;
        const float w00 = sw[o * 4 + 0], w01 = sw[o * 4 + 1];
        const float w10 = sw[o * 4 + 2], w11 = sw[o * 4 + 3];
        const float bb = sb[o];
        float* zr = z + zo * 304;
        for (int j = lane; j < 299; j += 32)
            zr[j] = bb + w00 * slo[j] + w01 * slo[j + 1]
                       + w10 * sro[j] + w11 * sro[j + 1];
        __syncwarp();
        const size_t obase = (size_t)n * YK + o * 297;
        for (int j = lane; j < 297; j += 32) {
            float v = fmaxf(fmaxf(zr[j], zr[j + 1]), fmaxf(zr[j + 2], 0.f));
            split_pair(v, g_yh[obase + j], g_yl[obase + j]);
        }
    }
}

// final: hidden = sum(hpart); i2h = sum(part)+l2b; out = relu((i2h+hidden)@ow^T+ob)
__global__ __launch_bounds__(512)
void out_kernel(const float* __restrict__ part,
                const float* __restrict__ hpart,
                const float* __restrict__ l2b,
                const float* __restrict__ ow,
                const float* __restrict__ ob,
                float* __restrict__ out,
                float* __restrict__ hidOut)
{
    __shared__ float val[HID];
    const int n   = blockIdx.x;
    const int tid = threadIdx.x;

    if (tid < HID) {
        const size_t o = (size_t)n * HID + tid;
        float hs = hpart[o];
        #pragma unroll
        for (int s = 1; s < CHS; ++s) hs += hpart[(size_t)s * NB * HID + o];
        float is = l2b[tid];
        #pragma unroll
        for (int s = 0; s < L2S; ++s) is += part[(size_t)s * NB * HID + o];
        hidOut[o] = hs;
        val[tid] = hs + is;
    }
    __syncthreads();

    if (tid < OUT * 32) {
        const int m    = tid >> 5;
        const int lane = tid & 31;
        const float* w = ow + (size_t)m * HID;
        float s = 0.f;
        for (int k = lane; k < HID; k += 32) s += val[k] * w[k];
        #pragma unroll
        for (int o = 16; o; o >>= 1) s += __shfl_down_sync(0xffffffffu, s, o);
        if (lane == 0) out[n * OUT + m] = fmaxf(s + ob[m], 0.f);
    }
}

// ---------------------------------------------------------------------------
static cudaStream_t s_side = nullptr;
static cudaEvent_t  s_evF  = nullptr;
static cudaEvent_t  s_evJ  = nullptr;
#define PP_SMEM (3 * 4 * ARRE * 2)   // 61440 bytes

extern "C" void kernel_launch(void* const* d_in, const int* in_sizes, int n_in,
                              void* d_out, int out_size)
{
    if (!s_side) {
        cudaStreamCreateWithFlags(&s_side, cudaStreamNonBlocking);
        cudaEventCreateWithFlags(&s_evF, cudaEventDisableTiming);
        cudaEventCreateWithFlags(&s_evJ, cudaEventDisableTiming);
        cudaFuncSetAttribute(pp_gemm, cudaFuncAttributeMaxDynamicSharedMemorySize, PP_SMEM);
        cudaFuncSetAttribute(pp_gemm, cudaFuncAttributePreferredSharedMemoryCarveout,
                             cudaSharedmemCarveoutMaxShared);
        cudaFuncSetAttribute(l2_gemm, cudaFuncAttributePreferredSharedMemoryCarveout,
                             cudaSharedmemCarveoutMaxShared);
        cudaFuncSetAttribute(fc_gemm, cudaFuncAttributePreferredSharedMemoryCarveout,
                             cudaSharedmemCarveoutMaxShared);
        cudaFuncSetAttribute(reduce_split<true>, cudaFuncAttributePreferredSharedMemoryCarveout,
                             cudaSharedmemCarveoutMaxShared);
        cudaFuncSetAttribute(reduce_split<false>, cudaFuncAttributePreferredSharedMemoryCarveout,
                             cudaSharedmemCarveoutMaxShared);
        cudaFuncSetAttribute(pad_kernel, cudaFuncAttributePreferredSharedMemoryCarveout,
                             cudaSharedmemCarveoutMaxShared);
        cudaFuncSetAttribute(hand_feat_kernel, cudaFuncAttributePreferredSharedMemoryCarveout,
                             cudaSharedmemCarveoutMaxShared);
        cudaFuncSetAttribute(conv2pool_kernel, cudaFuncAttributePreferredSharedMemoryCarveout,
                             cudaSharedmemCarveoutMaxShared);
        cudaFuncSetAttribute(out_kernel, cudaFuncAttributePreferredSharedMemoryCarveout,
                             cudaSharedmemCarveoutMaxShared);
    }

    const float* hand_data = (const float*)d_in[0];
    const float* hidden    = (const float*)d_in[1];
    const float* l_conv_w  = (const float*)d_in[2];
    const float* l_conv_b  = (const float*)d_in[3];
    const float* l_fc_w    = (const float*)d_in[4];
    const float* l_fc_b    = (const float*)d_in[5];
    const float* r_conv_w  = (const float*)d_in[6];
    const float* r_conv_b  = (const float*)d_in[7];
    const float* r_fc_w    = (const float*)d_in[8];
    const float* r_fc_b    = (const float*)d_in[9];
    const float* conv2_w   = (const float*)d_in[10];
    const float* conv2_b   = (const float*)d_in[11];
    const float* l2_w      = (const float*)d_in[12];
    const float* l2_b      = (const float*)d_in[13];
    const float* h2h_w     = (const float*)d_in[14];
    const float* h2h_b     = (const float*)d_in[15];
    const float* out_w     = (const float*)d_in[16];
    const float* out_b     = (const float*)d_in[17];

    const int T    = in_sizes[0] / (NB * 84);
    const int tOff = (T - 1) * NB * 84;

    bf *feath, *featl, *yh, *yl;
    bf *Wh, *Wl, *WTh, *WTl, *M0h, *M0l, *M0Th, *M0Tl, *M1h, *M1l, *M1Th, *M1Tl;
    bf *h0h, *h0l;
    float *both, *part, *cpart, *hpart, *hid;
    cudaGetSymbolAddress((void**)&feath, g_feath);
    cudaGetSymbolAddress((void**)&featl, g_featl);
    cudaGetSymbolAddress((void**)&both,  g_both);
    cudaGetSymbolAddress((void**)&yh,    g_yh);
    cudaGetSymbolAddress((void**)&yl,    g_yl);
    cudaGetSymbolAddress((void**)&part,  g_part);
    cudaGetSymbolAddress((void**)&cpart, g_cpart);
    cudaGetSymbolAddress((void**)&hpart, g_hpart);
    cudaGetSymbolAddress((void**)&Wh,    g_Wh);
    cudaGetSymbolAddress((void**)&Wl,    g_Wl);
    cudaGetSymbolAddress((void**)&WTh,   g_WTh);
    cudaGetSymbolAddress((void**)&WTl,   g_WTl);
    cudaGetSymbolAddress((void**)&M0h,   g_M0h);
    cudaGetSymbolAddress((void**)&M0l,   g_M0l);
    cudaGetSymbolAddress((void**)&M0Th,  g_M0Th);
    cudaGetSymbolAddress((void**)&M0Tl,  g_M0Tl);
    cudaGetSymbolAddress((void**)&M1h,   g_M1h);
    cudaGetSymbolAddress((void**)&M1l,   g_M1l);
    cudaGetSymbolAddress((void**)&M1Th,  g_M1Th);
    cudaGetSymbolAddress((void**)&M1Tl,  g_M1Tl);
    cudaGetSymbolAddress((void**)&h0h,   g_h0h);
    cudaGetSymbolAddress((void**)&h0l,   g_h0l);
    cudaGetSymbolAddress((void**)&hid,   g_hid);

    float* hidOut = (out_size >= NB * OUT + NB * HID) ? ((float*)d_out) + NB * OUT : hid;

    // fork side stream off the main stream head
    cudaEventRecord(s_evF, 0);
    cudaStreamWaitEvent(s_side, s_evF, 0);

    // ---- side stream: pad -> 5x (split-K squaring + reduce) -> hidden partials
    pad_kernel<<<(HIDP * HIDP + 255) / 256, 256, 0, s_side>>>(h2h_w, h2h_b, hidden);
    {
        const bf *sh = Wh, *sl = Wl, *sth = WTh, *stl = WTl;
        bf* dh [5] = { M0h,  M1h,  M0h,  M1h,  M0h  };
        bf* dl [5] = { M0l,  M1l,  M0l,  M1l,  M0l  };
        bf* dth[5] = { M0Th, M1Th, M0Th, M1Th, M0Th };
        bf* dtl[5] = { M0Tl, M1Tl, M0Tl, M1Tl, M0Tl };
        for (int i = 0; i < 5; ++i) {
            pp_gemm<<<dim3(8, 8, CHS), 256, PP_SMEM, s_side>>>(
                HIDP, HIDP, HIDP, sh, sl, HIDP, sth, stl, HIDP, cpart, HIDP, CHLEN);
            if (i < 4)
                reduce_split<true><<<dim3(16, 16), 256, 0, s_side>>>(
                    cpart, dh[i], dl[i], dth[i], dtl[i]);
            else
                reduce_split<false><<<dim3(16, 16), 256, 0, s_side>>>(
                    cpart, dh[i], dl[i], nullptr, nullptr);
            sh = dh[i]; sl = dl[i]; sth = dth[i]; stl = dtl[i];
        }
        // hidden partials = h0aug @ M32^T (bias via homogeneous column)
        pp_gemm<<<dim3(8, 8, CHS), 256, PP_SMEM, s_side>>>(
            NB, HID, HIDP, h0h, h0l, HIDP, M0h, M0l, HIDP, hpart, HID, CHLEN);
    }
    cudaEventRecord(s_evJ, s_side);

    // ---- main stream: data front-end
    hand_feat_kernel<<<1024, 128>>>(hand_data, l_conv_w, l_conv_b, r_conv_w, r_conv_b, tOff);
    fc_gemm<<<dim3(5, 16), 256>>>(feath, featl, l_fc_w, l_fc_b, r_fc_w, r_fc_b, both);
    conv2pool_kernel<<<dim3(NB, 2), 256>>>(conv2_w, conv2_b);
    l2_gemm<<<dim3(8, 8, L2S), 256>>>(yh, yl, l2_w, part);

    // ---- join + final fused kernel
    cudaStreamWaitEvent(0, s_evJ, 0);
    out_kernel<<<NB, 512>>>(part, hpart, l2_b, out_w, out_b, (float*)d_out, hidOut);
}

// round 17
// speedup vs baseline: 1.2938x; 1.0108x over previous
#include <cuda_runtime.h>
#include <cuda_bf16.h>

// ---------------------------------------------------------------------------
// ASLRNN3 sm_100a.  R16 base (147.2us) + BK=64 pp_gemm (chain + hidden):
// empirical law dur ~= waves*(1.2us + 1.0us*iters) with the per-iter term
// latency-bound -> halve iters by doubling BK. 2-stage x 36.9KB dynamic smem.
//  * only last frame feeds outs[-1]
//  * hidden recurrence: affine -> homogeneous 501x501 power, 5 squarings
//    (split-K=2 + reduce) on a side stream overlapped with the front-end.
//  * all GEMMs: bf16 hi/lo split 3-MMA, fp32 accum, cp.async, ldmatrix frags.
// ---------------------------------------------------------------------------

#define NB 512
#define FEAT 304
#define FEATP 320
#define HF 300
#define YK 9504
#define HID 500
#define HIDP 512
#define OUT 10
#define L2S 11         // l2 split-K  (9504 = 11*864)
#define L2LEN 864
#define CHS 2          // chain split-K (512 = 2*256) -> grid 128, one wave
#define CHLEN 256

typedef __nv_bfloat16 bf;

// ---- scratch ----
__device__ bf g_feath[1024 * FEATP];
__device__ bf g_featl[1024 * FEATP];
__device__ float g_both[1024 * HF];
__device__ bf g_yh[NB * YK];
__device__ bf g_yl[NB * YK];
__device__ float g_part[L2S * NB * HID];
__device__ float g_cpart[CHS * HIDP * HIDP];
__device__ float g_hpart[CHS * NB * HID];
__device__ bf g_Wh [HIDP * HIDP];
__device__ bf g_Wl [HIDP * HIDP];
__device__ bf g_WTh[HIDP * HIDP];
__device__ bf g_WTl[HIDP * HIDP];
__device__ bf g_M0h[HIDP * HIDP];
__device__ bf g_M0l[HIDP * HIDP];
__device__ bf g_M0Th[HIDP * HIDP];
__device__ bf g_M0Tl[HIDP * HIDP];
__device__ bf g_M1h[HIDP * HIDP];
__device__ bf g_M1l[HIDP * HIDP];
__device__ bf g_M1Th[HIDP * HIDP];
__device__ bf g_M1Tl[HIDP * HIDP];
__device__ bf g_h0h[NB * HIDP];
__device__ bf g_h0l[NB * HIDP];
__device__ float g_hid[NB * HID];

#define MMA16816(c, a, b) asm volatile( \
    "mma.sync.aligned.m16n8k16.row.col.f32.bf16.bf16.f32 " \
    "{%0,%1,%2,%3},{%4,%5,%6,%7},{%8,%9},{%0,%1,%2,%3};\n" \
    : "+f"((c)[0]), "+f"((c)[1]), "+f"((c)[2]), "+f"((c)[3]) \
    : "r"((a)[0]), "r"((a)[1]), "r"((a)[2]), "r"((a)[3]), \
      "r"((b)[0]), "r"((b)[1]))

__device__ __forceinline__ void split_pair(float x, bf& h, bf& l) {
    h = __float2bfloat16(x);
    l = __float2bfloat16(x - __bfloat162float(h));
}
__device__ __forceinline__ void cp16(unsigned dst, const void* src) {
    asm volatile("cp.async.ca.shared.global [%0], [%1], 16;\n" :: "r"(dst), "l"(src));
}
#define CP_COMMIT asm volatile("cp.async.commit_group;\n")

#define SA 40
#define ARRE (64 * SA)
#define SA64 72
#define ARRE64 (64 * SA64)

__device__ __forceinline__ void ldsm4(unsigned addr, unsigned* r) {
    asm volatile("ldmatrix.sync.aligned.m8n8.x4.shared.b16 {%0,%1,%2,%3}, [%4];"
        : "=r"(r[0]), "=r"(r[1]), "=r"(r[2]), "=r"(r[3]) : "r"(addr));
}

// hi/lo 3-MMA over NS 16-k-steps using ldmatrix fragment loads.
template<int ST, int ARR, int NS>
__device__ __forceinline__ void stage_mma_u(unsigned base, int wm, int wn,
                                            int lane, float acc[2][2][4])
{
    constexpr unsigned AB = ARR * 2;
    const int arow = lane & 15;
    const int acol = (lane >> 4) * 8;
    const int bg   = lane >> 3;
    const int brow = (bg >> 1) * 8 + (lane & 7);
    const int bcol = (bg & 1) * 8;
    #pragma unroll
    for (int s = 0; s < NS; ++s) {
        const int kb = s * 16;
        unsigned a_h[2][4], a_l[2][4], b_h[4], b_l[4];
        #pragma unroll
        for (int mt = 0; mt < 2; ++mt) {
            const unsigned ao = (unsigned)(((wm + mt * 16 + arow) * ST + kb + acol) * 2);
            ldsm4(base + ao,      a_h[mt]);
            ldsm4(base + AB + ao, a_l[mt]);
        }
        const unsigned bo = (unsigned)(((wn + brow) * ST + kb + bcol) * 2);
        ldsm4(base + 2 * AB + bo, b_h);
        ldsm4(base + 3 * AB + bo, b_l);
        #pragma unroll
        for (int mt = 0; mt < 2; ++mt)
            #pragma unroll
            for (int nt = 0; nt < 2; ++nt) {
                MMA16816(acc[mt][nt], a_h[mt], b_h + nt * 2);
                MMA16816(acc[mt][nt], a_h[mt], b_l + nt * 2);
                MMA16816(acc[mt][nt], a_l[mt], b_h + nt * 2);
            }
    }
}

// ---------------------------------------------------------------------------
// pp_gemm: pair A, pair B, split-K -> fp32 partials. BK=64, 2-stage cp.async
// in dynamic smem (73.7KB). K chunk % 64 == 0.
// ---------------------------------------------------------------------------
__global__ __launch_bounds__(256)
void pp_gemm(int M, int N, int K,
             const bf* __restrict__ Agh, const bf* __restrict__ Agl, int lda,
             const bf* __restrict__ Bgh, const bf* __restrict__ Bgl, int ldb,
             float* __restrict__ C, int ldc, int splitLen)
{
    extern __shared__ __align__(16) bf smd[];
    const unsigned smb = (unsigned)__cvta_generic_to_shared(smd);
    constexpr unsigned ARRB = ARRE64 * 2;
    constexpr unsigned STAGEB = 4 * ARRB;

    const int tid  = threadIdx.x;
    const int wid  = tid >> 5;
    const int lane = tid & 31;
    const int wm   = (wid >> 2) * 32;
    const int wn   = (wid & 3) * 16;
    const int lr   = lane >> 2;
    const int lc   = lane & 3;
    const int m0   = blockIdx.y * 64;
    const int n0   = blockIdx.x * 64;

    const int kbeg = blockIdx.z * splitLen;
    const int kend = min(K, kbeg + splitLen);
    C += (size_t)blockIdx.z * (size_t)M * (size_t)ldc;

    float acc[2][2][4] = {};
    const int ar = tid >> 2;              // 0..63
    const int ac = (tid & 3) * 16;        // 0,16,32,48

    auto issue = [&](int k0, int st) {
        const size_t ao = (size_t)(m0 + ar) * lda + k0 + ac;
        const size_t bo = (size_t)(n0 + ar) * ldb + k0 + ac;
        const unsigned d = smb + st * STAGEB + (unsigned)(ar * SA64 + ac) * 2;
        cp16(d,                 Agh + ao);
        cp16(d + 16,            Agh + ao + 8);
        cp16(d + ARRB,          Agl + ao);
        cp16(d + ARRB + 16,     Agl + ao + 8);
        cp16(d + 2 * ARRB,      Bgh + bo);
        cp16(d + 2 * ARRB + 16, Bgh + bo + 8);
        cp16(d + 3 * ARRB,      Bgl + bo);
        cp16(d + 3 * ARRB + 16, Bgl + bo + 8);
        CP_COMMIT;
    };

    const int nit = (kend - kbeg) / 64;
    issue(kbeg, 0);
    for (int i = 0; i < nit; ++i) {
        if (i + 1 < nit) {
            issue(kbeg + (i + 1) * 64, (i + 1) & 1);
            asm volatile("cp.async.wait_group 1;\n");
        } else {
            asm volatile("cp.async.wait_group 0;\n");
        }
        __syncthreads();
        stage_mma_u<SA64, ARRE64, 4>(smb + (i & 1) * STAGEB, wm, wn, lane, acc);
        __syncthreads();
    }

    #pragma unroll
    for (int mt = 0; mt < 2; ++mt)
        #pragma unroll
        for (int nt = 0; nt < 2; ++nt)
            #pragma unroll
            for (int rr = 0; rr < 2; ++rr) {
                const int r = m0 + wm + mt * 16 + lr + rr * 8;
                #pragma unroll
                for (int j = 0; j < 2; ++j) {
                    const int c = n0 + wn + nt * 8 + lc * 2 + j;
                    if (c < N) C[(size_t)r * ldc + c] = acc[mt][nt][rr * 2 + j];
                }
            }
}

// ---------------------------------------------------------------------------
// reduce CHS fp32 partials -> bf16 pair (+ optional transposed pair), 512x512
template<bool WRITET>
__global__ __launch_bounds__(256)
void reduce_split(const float* __restrict__ part,
                  bf* __restrict__ Dh, bf* __restrict__ Dl,
                  bf* __restrict__ DTh, bf* __restrict__ DTl)
{
    __shared__ bf th[32][33], tl[32][33];
    const int bx = blockIdx.x * 32, by = blockIdx.y * 32;
    const int x = threadIdx.x & 31;
    const int y0 = threadIdx.x >> 5;
    #pragma unroll
    for (int dy = 0; dy < 32; dy += 8) {
        const int r = by + y0 + dy, c = bx + x;
        const size_t idx = (size_t)r * HIDP + c;
        float v = part[idx];
        #pragma unroll
        for (int s = 1; s < CHS; ++s) v += part[(size_t)s * HIDP * HIDP + idx];
        bf h, l;
        split_pair(v, h, l);
        Dh[idx] = h; Dl[idx] = l;
        th[y0 + dy][x] = h; tl[y0 + dy][x] = l;
    }
    if (WRITET) {
        __syncthreads();
        #pragma unroll
        for (int dy = 0; dy < 32; dy += 8) {
            const int r = bx + y0 + dy, c = by + x;
            const size_t idx = (size_t)r * HIDP + c;
            DTh[idx] = th[x][y0 + dy];
            DTl[idx] = tl[x][y0 + dy];
        }
    }
}

// ---------------------------------------------------------------------------
// l2_gemm: pair A (cp.async), fp32 B (register-prefetch + split in staging),
// split-K -> fp32 partials. B is (N,K)=(500,9504) row-major fp32.
// ---------------------------------------------------------------------------
__global__ __launch_bounds__(256)
void l2_gemm(const bf* __restrict__ Agh, const bf* __restrict__ Agl,
             const float* __restrict__ Bf,
             float* __restrict__ C)
{
    __shared__ __align__(16) bf sm[2 * 4 * ARRE];
    const unsigned smb = (unsigned)__cvta_generic_to_shared(sm);
    constexpr unsigned ARRB = ARRE * 2;
    constexpr unsigned STAGEB = 4 * ARRB;

    const int tid  = threadIdx.x;
    const int wid  = tid >> 5;
    const int lane = tid & 31;
    const int wm   = (wid >> 2) * 32;
    const int wn   = (wid & 3) * 16;
    const int lr   = lane >> 2;
    const int lc   = lane & 3;
    const int m0   = blockIdx.y * 64;
    const int n0   = blockIdx.x * 64;
    const int kbeg = blockIdx.z * L2LEN;
    C += (size_t)blockIdx.z * (size_t)NB * (size_t)HID;

    float acc[2][2][4] = {};
    const int ar = tid >> 2;
    const int ac = (tid & 3) * 8;
    const bool bvalid = (n0 + ar) < HID;
    const float* brow = Bf + (size_t)(n0 + ar) * YK;

    float4 rB0, rB1;

    auto issueA = [&](int k0, int st) {
        const size_t ao = (size_t)(m0 + ar) * YK + k0 + ac;
        const unsigned d = smb + st * STAGEB + (unsigned)(ar * SA + ac) * 2;
        cp16(d,        Agh + ao);
        cp16(d + ARRB, Agl + ao);
        CP_COMMIT;
    };
    auto loadB = [&](int k0) {
        if (bvalid) {
            rB0 = *reinterpret_cast<const float4*>(brow + k0 + ac);
            rB1 = *reinterpret_cast<const float4*>(brow + k0 + ac + 4);
        } else {
            rB0 = make_float4(0.f, 0.f, 0.f, 0.f);
            rB1 = make_float4(0.f, 0.f, 0.f, 0.f);
        }
    };
    auto storeB = [&](int st) {
        bf* Bh = sm + st * 4 * ARRE + 2 * ARRE + ar * SA + ac;
        bf* Bl = Bh + ARRE;
        const float v[8] = { rB0.x, rB0.y, rB0.z, rB0.w, rB1.x, rB1.y, rB1.z, rB1.w };
        uint4 vh, vl;
        bf* hv = reinterpret_cast<bf*>(&vh);
        bf* lv = reinterpret_cast<bf*>(&vl);
        #pragma unroll
        for (int e = 0; e < 8; ++e) split_pair(v[e], hv[e], lv[e]);
        *reinterpret_cast<uint4*>(Bh) = vh;
        *reinterpret_cast<uint4*>(Bl) = vl;
    };

    constexpr int nit = L2LEN / 32;
    issueA(kbeg, 0);
    loadB(kbeg);
    for (int i = 0; i < nit; ++i) {
        if (i + 1 < nit) issueA(kbeg + (i + 1) * 32, (i + 1) & 1);
        storeB(i & 1);
        if (i + 1 < nit) asm volatile("cp.async.wait_group 1;\n");
        else             asm volatile("cp.async.wait_group 0;\n");
        __syncthreads();
        if (i + 1 < nit) loadB(kbeg + (i + 1) * 32);
        stage_mma_u<SA, ARRE, 2>(smb + (i & 1) * STAGEB, wm, wn, lane, acc);
        __syncthreads();
    }

    #pragma unroll
    for (int mt = 0; mt < 2; ++mt)
        #pragma unroll
        for (int nt = 0; nt < 2; ++nt)
            #pragma unroll
            for (int rr = 0; rr < 2; ++rr) {
                const int r = m0 + wm + mt * 16 + lr + rr * 8;
                #pragma unroll
                for (int j = 0; j < 2; ++j) {
                    const int c = n0 + wn + nt * 8 + lc * 2 + j;
                    if (c < HID) C[(size_t)r * HID + c] = acc[mt][nt][rr * 2 + j];
                }
            }
}

// ---------------------------------------------------------------------------
// fc GEMM: K=FEATP=320, BK=32, cp.async 2-stage A + register fp32 dual B.
__global__ __launch_bounds__(256)
void fc_gemm(const bf* __restrict__ Agh, const bf* __restrict__ Agl,
             const float* __restrict__ Bf, const float* __restrict__ bias,
             const float* __restrict__ Bf2, const float* __restrict__ bias2,
             float* __restrict__ C)
{
    __shared__ __align__(16) bf sm[2 * 4 * ARRE];
    const unsigned smb = (unsigned)__cvta_generic_to_shared(sm);
    constexpr unsigned ARRB = ARRE * 2;
    constexpr unsigned STAGEB = 4 * ARRB;

    const int tid  = threadIdx.x;
    const int wid  = tid >> 5;
    const int lane = tid & 31;
    const int wm   = (wid >> 2) * 32;
    const int wn   = (wid & 3) * 16;
    const int lr   = lane >> 2;
    const int lc   = lane & 3;
    const int m0   = blockIdx.y * 64;
    const int n0   = blockIdx.x * 64;
    const int N = HF;

    if (blockIdx.y >= (gridDim.y >> 1)) { Bf = Bf2; bias = bias2; }

    float acc[2][2][4] = {};
    const int ar = tid >> 2;
    const int ac = (tid & 3) * 8;
    const bool bvalid = (n0 + ar) < N;
    const float* brow = Bf + (size_t)(n0 + ar) * FEAT;

    float4 rB0, rB1;

    auto issueA = [&](int k0, int st) {
        const size_t ao = (size_t)(m0 + ar) * FEATP + k0 + ac;
        const unsigned d = smb + st * STAGEB + (unsigned)(ar * SA + ac) * 2;
        cp16(d,        Agh + ao);
        cp16(d + ARRB, Agl + ao);
        CP_COMMIT;
    };
    auto loadB = [&](int k0) {
        rB0 = make_float4(0.f, 0.f, 0.f, 0.f);
        rB1 = make_float4(0.f, 0.f, 0.f, 0.f);
        if (bvalid) {
            const int k = k0 + ac;
            if (k + 3 < FEAT) rB0 = *reinterpret_cast<const float4*>(brow + k);
            if (k + 7 < FEAT) rB1 = *reinterpret_cast<const float4*>(brow + k + 4);
        }
    };
    auto storeB = [&](int st) {
        bf* Bh = sm + st * 4 * ARRE + 2 * ARRE + ar * SA + ac;
        bf* Bl = Bh + ARRE;
        const float v[8] = { rB0.x, rB0.y, rB0.z, rB0.w, rB1.x, rB1.y, rB1.z, rB1.w };
        uint4 vh, vl;
        bf* hv = reinterpret_cast<bf*>(&vh);
        bf* lv = reinterpret_cast<bf*>(&vl);
        #pragma unroll
        for (int e = 0; e < 8; ++e) split_pair(v[e], hv[e], lv[e]);
        *reinterpret_cast<uint4*>(Bh) = vh;
        *reinterpret_cast<uint4*>(Bl) = vl;
    };

    constexpr int nit = FEATP / 32;      // 10
    issueA(0, 0);
    loadB(0);
    for (int i = 0; i < nit; ++i) {
        if (i + 1 < nit) issueA((i + 1) * 32, (i + 1) & 1);
        storeB(i & 1);
        if (i + 1 < nit) asm volatile("cp.async.wait_group 1;\n");
        else             asm volatile("cp.async.wait_group 0;\n");
        __syncthreads();
        if (i + 1 < nit) loadB((i + 1) * 32);
        stage_mma_u<SA, ARRE, 2>(smb + (i & 1) * STAGEB, wm, wn, lane, acc);
        __syncthreads();
    }

    #pragma unroll
    for (int mt = 0; mt < 2; ++mt)
        #pragma unroll
        for (int nt = 0; nt < 2; ++nt)
            #pragma unroll
            for (int rr = 0; rr < 2; ++rr) {
                const int r = m0 + wm + mt * 16 + lr + rr * 8;
                #pragma unroll
                for (int j = 0; j < 2; ++j) {
                    const int c = n0 + wn + nt * 8 + lc * 2 + j;
                    if (c < N)
                        C[(size_t)r * HF + c] = fmaxf(acc[mt][nt][rr * 2 + j] + bias[c], 0.f);
                }
            }
}

// ---------------------------------------------------------------------------
__global__ void pad_kernel(const float* __restrict__ W,
                           const float* __restrict__ b,
                           const float* __restrict__ h0)
{
    int idx = blockIdx.x * blockDim.x + threadIdx.x;
    if (idx >= HIDP * HIDP) return;
    int r = idx >> 9, c = idx & (HIDP - 1);
    float wv = 0.f;
    if (r < HID) {
        if (c < HID) wv = W[r * HID + c];
        else if (c == HID) wv = b[r];
    } else if (r == HID && c == HID) wv = 1.f;
    bf h, l;
    split_pair(wv, h, l);
    g_Wh[idx] = h;  g_Wl[idx] = l;
    g_WTh[c * HIDP + r] = h;  g_WTl[c * HIDP + r] = l;
    float hv = (c < HID) ? h0[r * HID + c] : (c == HID ? 1.f : 0.f);
    split_pair(hv, g_h0h[idx], g_h0l[idx]);
}

// hand branch: conv1d(k=2,2->16) + relu + pool2 -> feat pair (320-padded)
__global__ void hand_feat_kernel(const float* __restrict__ hd,
                                 const float* __restrict__ lcw, const float* __restrict__ lcb,
                                 const float* __restrict__ rcw, const float* __restrict__ rcb,
                                 int tOff)
{
    const int s    = blockIdx.x;
    const int n    = s & (NB - 1);
    const int hand = s >> 9;
    const float* x  = hd + tOff + n * 84 + hand * 42;
    const float* cw = hand ? rcw : lcw;
    const float* cb = hand ? rcb : lcb;

    __shared__ float xs[42];
    __shared__ float z[16 * 20];
    const int tid = threadIdx.x;
    if (tid < 42) xs[tid] = x[tid];
    __syncthreads();

    for (int idx = tid; idx < 320; idx += 128) {
        int o = idx / 20, j = idx % 20;
        float v = cb[o]
                + cw[o * 4 + 0] * xs[2 * j]
                + cw[o * 4 + 1] * xs[2 * j + 2]
                + cw[o * 4 + 2] * xs[2 * j + 1]
                + cw[o * 4 + 3] * xs[2 * j + 3];
        z[o * 20 + j] = fmaxf(v, 0.f);
    }
    __syncthreads();

    for (int idx = tid; idx < FEATP; idx += 128) {
        float v = 0.f;
        if (idx < FEAT) {
            int o = idx / 19, j = idx % 19;
            v = fmaxf(z[o * 20 + j], z[o * 20 + j + 1]);
        }
        split_pair(v, g_feath[(size_t)s * FEATP + idx], g_featl[(size_t)s * FEATP + idx]);
    }
}

// conv2(k=2,2->32) + relu + pool3 -> y pair; 2 blocks per sample (16 ch each).
__global__ __launch_bounds__(256)
void conv2pool_kernel(const float* __restrict__ w2, const float* __restrict__ b2)
{
    __shared__ float slo[HF], sro[HF], sw[128], sb[32];
    __shared__ float z[16 * 304];
    const int n    = blockIdx.x;
    const int half = blockIdx.y;
    const int tid  = threadIdx.x;
    const int wid  = tid >> 5;
    const int lane = tid & 31;
    for (int i = tid; i < HF; i += 256) {
        slo[i] = g_both[(size_t)n * HF + i];
        sro[i] = g_both[(size_t)(NB + n) * HF + i];
    }
    if (tid < 128) sw[tid] = w2[tid];
    if (tid < 32)  sb[tid] = b2[tid];
    __syncthreads();

    #pragma unroll
    for (int oo = 0; oo < 2; ++oo) {
        const int zo = oo * 8 + wid;
        const int o  = half * 16 + zo;
        const float w00 = sw[o * 4 + 0], w01 = sw[o * 4 + 1];
        const float w10 = sw[o * 4 + 2], w11 = sw[o * 4 + 3];
        const float bb = sb[o];
        float* zr = z + zo * 304;
        for (int j = lane; j < 299; j += 32)
            zr[j] = bb + w00 * slo[j] + w01 * slo[j + 1]
                       + w10 * sro[j] + w11 * sro[j + 1];
        __syncwarp();
        const size_t obase = (size_t)n * YK + o * 297;
        for (int j = lane; j < 297; j += 32) {
            float v = fmaxf(fmaxf(zr[j], zr[j + 1]), fmaxf(zr[j + 2], 0.f));
            split_pair(v, g_yh[obase + j], g_yl[obase + j]);
        }
    }
}

// final: hidden = sum(hpart); i2h = sum(part)+l2b; out = relu((i2h+hidden)@ow^T+ob)
__global__ __launch_bounds__(512)
void out_kernel(const float* __restrict__ part,
                const float* __restrict__ hpart,
                const float* __restrict__ l2b,
                const float* __restrict__ ow,
                const float* __restrict__ ob,
                float* __restrict__ out,
                float* __restrict__ hidOut)
{
    __shared__ float val[HID];
    const int n   = blockIdx.x;
    const int tid = threadIdx.x;

    if (tid < HID) {
        const size_t o = (size_t)n * HID + tid;
        float hs = hpart[o];
        #pragma unroll
        for (int s = 1; s < CHS; ++s) hs += hpart[(size_t)s * NB * HID + o];
        float is = l2b[tid];
        #pragma unroll
        for (int s = 0; s < L2S; ++s) is += part[(size_t)s * NB * HID + o];
        hidOut[o] = hs;
        val[tid] = hs + is;
    }
    __syncthreads();

    if (tid < OUT * 32) {
        const int m    = tid >> 5;
        const int lane = tid & 31;
        const float* w = ow + (size_t)m * HID;
        float s = 0.f;
        for (int k = lane; k < HID; k += 32) s += val[k] * w[k];
        #pragma unroll
        for (int o = 16; o; o >>= 1) s += __shfl_down_sync(0xffffffffu, s, o);
        if (lane == 0) out[n * OUT + m] = fmaxf(s + ob[m], 0.f);
    }
}

// ---------------------------------------------------------------------------
static cudaStream_t s_side = nullptr;
static cudaEvent_t  s_evF  = nullptr;
static cudaEvent_t  s_evJ  = nullptr;
#define PP_SMEM (2 * 4 * ARRE64 * 2)   // 73728 bytes

extern "C" void kernel_launch(void* const* d_in, const int* in_sizes, int n_in,
                              void* d_out, int out_size)
{
    if (!s_side) {
        cudaStreamCreateWithFlags(&s_side, cudaStreamNonBlocking);
        cudaEventCreateWithFlags(&s_evF, cudaEventDisableTiming);
        cudaEventCreateWithFlags(&s_evJ, cudaEventDisableTiming);
        cudaFuncSetAttribute(pp_gemm, cudaFuncAttributeMaxDynamicSharedMemorySize, PP_SMEM);
        cudaFuncSetAttribute(pp_gemm, cudaFuncAttributePreferredSharedMemoryCarveout,
                             cudaSharedmemCarveoutMaxShared);
        cudaFuncSetAttribute(l2_gemm, cudaFuncAttributePreferredSharedMemoryCarveout,
                             cudaSharedmemCarveoutMaxShared);
        cudaFuncSetAttribute(fc_gemm, cudaFuncAttributePreferredSharedMemoryCarveout,
                             cudaSharedmemCarveoutMaxShared);
        cudaFuncSetAttribute(reduce_split<true>, cudaFuncAttributePreferredSharedMemoryCarveout,
                             cudaSharedmemCarveoutMaxShared);
        cudaFuncSetAttribute(reduce_split<false>, cudaFuncAttributePreferredSharedMemoryCarveout,
                             cudaSharedmemCarveoutMaxShared);
        cudaFuncSetAttribute(pad_kernel, cudaFuncAttributePreferredSharedMemoryCarveout,
                             cudaSharedmemCarveoutMaxShared);
        cudaFuncSetAttribute(hand_feat_kernel, cudaFuncAttributePreferredSharedMemoryCarveout,
                             cudaSharedmemCarveoutMaxShared);
        cudaFuncSetAttribute(conv2pool_kernel, cudaFuncAttributePreferredSharedMemoryCarveout,
                             cudaSharedmemCarveoutMaxShared);
        cudaFuncSetAttribute(out_kernel, cudaFuncAttributePreferredSharedMemoryCarveout,
                             cudaSharedmemCarveoutMaxShared);
    }

    const float* hand_data = (const float*)d_in[0];
    const float* hidden    = (const float*)d_in[1];
    const float* l_conv_w  = (const float*)d_in[2];
    const float* l_conv_b  = (const float*)d_in[3];
    const float* l_fc_w    = (const float*)d_in[4];
    const float* l_fc_b    = (const float*)d_in[5];
    const float* r_conv_w  = (const float*)d_in[6];
    const float* r_conv_b  = (const float*)d_in[7];
    const float* r_fc_w    = (const float*)d_in[8];
    const float* r_fc_b    = (const float*)d_in[9];
    const float* conv2_w   = (const float*)d_in[10];
    const float* conv2_b   = (const float*)d_in[11];
    const float* l2_w      = (const float*)d_in[12];
    const float* l2_b      = (const float*)d_in[13];
    const float* h2h_w     = (const float*)d_in[14];
    const float* h2h_b     = (const float*)d_in[15];
    const float* out_w     = (const float*)d_in[16];
    const float* out_b     = (const float*)d_in[17];

    const int T    = in_sizes[0] / (NB * 84);
    const int tOff = (T - 1) * NB * 84;

    bf *feath, *featl, *yh, *yl;
    bf *Wh, *Wl, *WTh, *WTl, *M0h, *M0l, *M0Th, *M0Tl, *M1h, *M1l, *M1Th, *M1Tl;
    bf *h0h, *h0l;
    float *both, *part, *cpart, *hpart, *hid;
    cudaGetSymbolAddress((void**)&feath, g_feath);
    cudaGetSymbolAddress((void**)&featl, g_featl);
    cudaGetSymbolAddress((void**)&both,  g_both);
    cudaGetSymbolAddress((void**)&yh,    g_yh);
    cudaGetSymbolAddress((void**)&yl,    g_yl);
    cudaGetSymbolAddress((void**)&part,  g_part);
    cudaGetSymbolAddress((void**)&cpart, g_cpart);
    cudaGetSymbolAddress((void**)&hpart, g_hpart);
    cudaGetSymbolAddress((void**)&Wh,    g_Wh);
    cudaGetSymbolAddress((void**)&Wl,    g_Wl);
    cudaGetSymbolAddress((void**)&WTh,   g_WTh);
    cudaGetSymbolAddress((void**)&WTl,   g_WTl);
    cudaGetSymbolAddress((void**)&M0h,   g_M0h);
    cudaGetSymbolAddress((void**)&M0l,   g_M0l);
    cudaGetSymbolAddress((void**)&M0Th,  g_M0Th);
    cudaGetSymbolAddress((void**)&M0Tl,  g_M0Tl);
    cudaGetSymbolAddress((void**)&M1h,   g_M1h);
    cudaGetSymbolAddress((void**)&M1l,   g_M1l);
    cudaGetSymbolAddress((void**)&M1Th,  g_M1Th);
    cudaGetSymbolAddress((void**)&M1Tl,  g_M1Tl);
    cudaGetSymbolAddress((void**)&h0h,   g_h0h);
    cudaGetSymbolAddress((void**)&h0l,   g_h0l);
    cudaGetSymbolAddress((void**)&hid,   g_hid);

    float* hidOut = (out_size >= NB * OUT + NB * HID) ? ((float*)d_out) + NB * OUT : hid;

    // fork side stream off the main stream head
    cudaEventRecord(s_evF, 0);
    cudaStreamWaitEvent(s_side, s_evF, 0);

    // ---- side stream: pad -> 5x (split-K squaring + reduce) -> hidden partials
    pad_kernel<<<(HIDP * HIDP + 255) / 256, 256, 0, s_side>>>(h2h_w, h2h_b, hidden);
    {
        const bf *sh = Wh, *sl = Wl, *sth = WTh, *stl = WTl;
        bf* dh [5] = { M0h,  M1h,  M0h,  M1h,  M0h  };
        bf* dl [5] = { M0l,  M1l,  M0l,  M1l,  M0l  };
        bf* dth[5] = { M0Th, M1Th, M0Th, M1Th, M0Th };
        bf* dtl[5] = { M0Tl, M1Tl, M0Tl, M1Tl, M0Tl };
        for (int i = 0; i < 5; ++i) {
            pp_gemm<<<dim3(8, 8, CHS), 256, PP_SMEM, s_side>>>(
                HIDP, HIDP, HIDP, sh, sl, HIDP, sth, stl, HIDP, cpart, HIDP, CHLEN);
            if (i < 4)
                reduce_split<true><<<dim3(16, 16), 256, 0, s_side>>>(
                    cpart, dh[i], dl[i], dth[i], dtl[i]);
            else
                reduce_split<false><<<dim3(16, 16), 256, 0, s_side>>>(
                    cpart, dh[i], dl[i], nullptr, nullptr);
            sh = dh[i]; sl = dl[i]; sth = dth[i]; stl = dtl[i];
        }
        // hidden partials = h0aug @ M32^T (bias via homogeneous column)
        pp_gemm<<<dim3(8, 8, CHS), 256, PP_SMEM, s_side>>>(
            NB, HID, HIDP, h0h, h0l, HIDP, M0h, M0l, HIDP, hpart, HID, CHLEN);
    }
    cudaEventRecord(s_evJ, s_side);

    // ---- main stream: data front-end
    hand_feat_kernel<<<1024, 128>>>(hand_data, l_conv_w, l_conv_b, r_conv_w, r_conv_b, tOff);
    fc_gemm<<<dim3(5, 16), 256>>>(feath, featl, l_fc_w, l_fc_b, r_fc_w, r_fc_b, both);
    conv2pool_kernel<<<dim3(NB, 2), 256>>>(conv2_w, conv2_b);
    l2_gemm<<<dim3(8, 8, L2S), 256>>>(yh, yl, l2_w, part);

    // ---- join + final fused kernel
    cudaStreamWaitEvent(0, s_evJ, 0);
    out_kernel<<<NB, 512>>>(part, hpart, l2_b, out_w, out_b, (float*)d_out, hidOut);
}